// round 1
// baseline (speedup 1.0000x reference)
#include <cuda_runtime.h>
#include <math.h>
#include <stdint.h>

#define NNODES 50000
#define NEDGES 600000
#define DM 128
#define HH 8
#define DH 16
#define DFFH 512
#define LL 3

// ---------------- scratch (static device memory; no allocs allowed) --------
__device__ float g_z[(size_t)NNODES * DM];       // projected features z = x@W
__device__ float g_el[(size_t)NNODES * HH];
__device__ float g_er[(size_t)NNODES * HH];
__device__ float g_e[(size_t)NEDGES * HH];       // edge logits, then exp values
__device__ float g_emax[(size_t)NNODES * HH];
__device__ float g_denom[(size_t)NNODES * HH];
__device__ float g_agg[(size_t)NNODES * DM];     // scatter accumulator
__device__ float g_h[(size_t)NNODES * DM];       // post-GAT layernorm output
__device__ float g_hn[(size_t)NNODES * DM];      // second layernorm output
__device__ float g_t[(size_t)NNODES * DFFH];     // FF hidden

// ---------------- helpers ---------------------------------------------------
__device__ __forceinline__ void atomicMaxFloat(float* addr, float value) {
    unsigned int* ua = (unsigned int*)addr;
    unsigned int old = *ua;
    while (__uint_as_float(old) < value) {
        unsigned int assumed = old;
        old = atomicCAS(ua, assumed, __float_as_uint(value));
        if (old == assumed) break;
    }
}

// block of 128 threads: reduce (a,b) as sums over the block; result broadcast.
__device__ __forceinline__ void blockReduce2_128(float& a, float& b, float* sm) {
    __syncthreads();  // protect sm reuse across calls
    #pragma unroll
    for (int o = 16; o > 0; o >>= 1) {
        a += __shfl_down_sync(0xFFFFFFFFu, a, o);
        b += __shfl_down_sync(0xFFFFFFFFu, b, o);
    }
    int w = threadIdx.x >> 5, lane = threadIdx.x & 31;
    if (lane == 0) { sm[w] = a; sm[4 + w] = b; }
    __syncthreads();
    if (threadIdx.x < 32) {
        a = (lane < 4) ? sm[lane] : 0.0f;
        b = (lane < 4) ? sm[4 + lane] : 0.0f;
        #pragma unroll
        for (int o = 2; o > 0; o >>= 1) {
            a += __shfl_down_sync(0xFFFFFFFFu, a, o);
            b += __shfl_down_sync(0xFFFFFFFFu, b, o);
        }
        if (lane == 0) { sm[0] = a; sm[1] = b; }
    }
    __syncthreads();
    a = sm[0];
    b = sm[1];
}

// ---------------- SGEMM: C[M,Nc] = A[M,K] @ B[K,Nc] (+epilogue) -------------
// MODE 0: C = acc                                 (z projection)
// MODE 1: C = prelu(acc + bias[col], *slope)      (FF first layer)
// MODE 2: C = acc + bias[col] + addend[row,col]   (FF second layer + residual)
template <int MODE>
__global__ void __launch_bounds__(256) sgemm64(
    const float* __restrict__ A, const float* __restrict__ B,
    float* __restrict__ C, int M, int Nc, int K,
    const float* __restrict__ bias, const float* __restrict__ slope,
    const float* __restrict__ addend)
{
    __shared__ float As[64][17];
    __shared__ float Bs[16][64];

    const int tx = threadIdx.x & 15;
    const int ty = threadIdx.x >> 4;
    const int rowBase = blockIdx.y * 64;
    const int colBase = blockIdx.x * 64;

    const int lin = threadIdx.x;
    const int ar = lin >> 2;          // 0..63 A-row within tile
    const int aq = (lin & 3) * 4;     // float4 slot in K16
    const int br = lin >> 4;          // 0..15 B-row within k-tile
    const int bq = (lin & 15) * 4;    // float4 slot in 64 cols

    float acc[4][4];
    #pragma unroll
    for (int i = 0; i < 4; i++)
        #pragma unroll
        for (int j = 0; j < 4; j++) acc[i][j] = 0.0f;

    for (int k0 = 0; k0 < K; k0 += 16) {
        float4 av = make_float4(0.f, 0.f, 0.f, 0.f);
        int grow = rowBase + ar;
        if (grow < M)
            av = *(const float4*)(A + (size_t)grow * K + k0 + aq);
        As[ar][aq + 0] = av.x; As[ar][aq + 1] = av.y;
        As[ar][aq + 2] = av.z; As[ar][aq + 3] = av.w;

        float4 bv = *(const float4*)(B + (size_t)(k0 + br) * Nc + colBase + bq);
        *(float4*)&Bs[br][bq] = bv;
        __syncthreads();

        #pragma unroll
        for (int kk = 0; kk < 16; kk++) {
            float a[4], b[4];
            #pragma unroll
            for (int i = 0; i < 4; i++) a[i] = As[ty * 4 + i][kk];
            #pragma unroll
            for (int j = 0; j < 4; j++) b[j] = Bs[kk][tx * 4 + j];
            #pragma unroll
            for (int i = 0; i < 4; i++)
                #pragma unroll
                for (int j = 0; j < 4; j++)
                    acc[i][j] = fmaf(a[i], b[j], acc[i][j]);
        }
        __syncthreads();
    }

    float slp = 0.0f;
    if (MODE == 1) slp = *slope;

    #pragma unroll
    for (int i = 0; i < 4; i++) {
        int r = rowBase + ty * 4 + i;
        if (r >= M) continue;
        #pragma unroll
        for (int j = 0; j < 4; j++) {
            int c = colBase + tx * 4 + j;
            float v = acc[i][j];
            if (MODE == 0) {
                C[(size_t)r * Nc + c] = v;
            } else if (MODE == 1) {
                v += bias[c];
                C[(size_t)r * Nc + c] = (v >= 0.0f) ? v : slp * v;
            } else {
                v += bias[c];
                v += addend[(size_t)r * Nc + c];
                C[(size_t)r * Nc + c] = v;
            }
        }
    }
}

// ---------------- per-node attention coefficients + init -------------------
__global__ void elr_kernel(const float* __restrict__ attn_l,
                           const float* __restrict__ attn_r)
{
    int idx = blockIdx.x * blockDim.x + threadIdx.x;
    if (idx >= NNODES * HH) return;
    int n = idx >> 3, h = idx & 7;
    const float* zp = g_z + (size_t)n * DM + h * DH;
    float sl = 0.f, sr = 0.f;
    #pragma unroll
    for (int d = 0; d < DH; d++) {
        float zv = zp[d];
        sl += zv * attn_l[h * DH + d];
        sr += zv * attn_r[h * DH + d];
    }
    g_el[idx] = sl;
    g_er[idx] = sr;
    g_emax[idx]  = -INFINITY;
    g_denom[idx] = 0.0f;
}

// ---------------- edge pass 1: logits + segment max -------------------------
__global__ void edge_att(const int* __restrict__ src, const int* __restrict__ dst)
{
    int idx = blockIdx.x * blockDim.x + threadIdx.x;
    if (idx >= NEDGES * HH) return;
    int e = idx >> 3, h = idx & 7;
    int s = src[e], d = dst[e];
    float v = g_el[s * HH + h] + g_er[d * HH + h];
    v = (v >= 0.0f) ? v : 0.2f * v;      // leaky_relu 0.2
    g_e[idx] = v;
    atomicMaxFloat(&g_emax[d * HH + h], v);
}

// ---------------- edge pass 2: exp + denom ----------------------------------
__global__ void edge_exp(const int* __restrict__ dst)
{
    int idx = blockIdx.x * blockDim.x + threadIdx.x;
    if (idx >= NEDGES * HH) return;
    int e = idx >> 3, h = idx & 7;
    int d = dst[e];
    float m = g_emax[d * HH + h];        // finite: dst has >=1 edge
    float ex = expf(g_e[idx] - m);
    g_e[idx] = ex;
    atomicAdd(&g_denom[d * HH + h], ex);
}

// ---------------- edge pass 3: weighted scatter ------------------------------
__global__ void edge_scatter(const int* __restrict__ src, const int* __restrict__ dst)
{
    int idx = blockIdx.x * blockDim.x + threadIdx.x;
    if (idx >= NEDGES * HH) return;
    int e = idx >> 3, h = idx & 7;
    int s = src[e], d = dst[e];
    float ex = g_e[idx];
    const float4* zp = (const float4*)(g_z + (size_t)s * DM + h * DH);
    float* ap = g_agg + (size_t)d * DM + h * DH;
    #pragma unroll
    for (int q = 0; q < 4; q++) {
        float4 zv = zp[q];
        float x = ex * zv.x, y = ex * zv.y, zz = ex * zv.z, w = ex * zv.w;
        asm volatile("red.global.add.v4.f32 [%0], {%1, %2, %3, %4};"
                     :: "l"(ap + q * 4), "f"(x), "f"(y), "f"(zz), "f"(w)
                     : "memory");
    }
}

// ---------------- normalize + PReLU + 2x LayerNorm ---------------------------
__global__ void __launch_bounds__(128) node_ln(
    const float* __restrict__ conv_bias, const float* __restrict__ a_conv,
    const float* __restrict__ ln_scale,  const float* __restrict__ ln_bias)
{
    __shared__ float sm[8];
    int n = blockIdx.x;
    int c = threadIdx.x;         // 0..127
    int h = c >> 4;

    float den = fmaxf(g_denom[n * HH + h], 1e-9f);
    float v = g_agg[(size_t)n * DM + c] / den + conv_bias[c];
    float a = *a_conv;
    v = (v >= 0.0f) ? v : a * v;

    // LayerNorm 1
    float s = v, s2 = v * v;
    blockReduce2_128(s, s2, sm);
    float m = s * (1.0f / DM);
    float var = s2 * (1.0f / DM) - m * m;
    float hv = (v - m) * rsqrtf(var + 1e-5f) * ln_scale[c] + ln_bias[c];
    g_h[(size_t)n * DM + c] = hv;

    // LayerNorm 2 (same params, on h)
    float t = hv, t2 = hv * hv;
    blockReduce2_128(t, t2, sm);
    float m2 = t * (1.0f / DM);
    float var2 = t2 * (1.0f / DM) - m2 * m2;
    float hn = (hv - m2) * rsqrtf(var2 + 1e-5f) * ln_scale[c] + ln_bias[c];
    g_hn[(size_t)n * DM + c] = hn;
}

// ---------------- launcher ---------------------------------------------------
extern "C" void kernel_launch(void* const* d_in, const int* in_sizes, int n_in,
                              void* d_out, int out_size)
{
    const float* in_feats = (const float*)d_in[0];
    const int*   src      = (const int*)  d_in[1];
    const int*   dst      = (const int*)  d_in[2];
    const float* W        = (const float*)d_in[3];   // [L,128,128]
    const float* attn_l   = (const float*)d_in[4];   // [L,8,16]
    const float* attn_r   = (const float*)d_in[5];
    const float* conv_b   = (const float*)d_in[6];   // [L,8,16] == [L,128]
    const float* a_conv   = (const float*)d_in[7];   // [L]
    const float* ln_scale = (const float*)d_in[8];   // [L,128]
    const float* ln_bias  = (const float*)d_in[9];
    const float* W1       = (const float*)d_in[10];  // [L,128,512]
    const float* b1       = (const float*)d_in[11];  // [L,512]
    const float* W2       = (const float*)d_in[12];  // [L,512,128]
    const float* b2       = (const float*)d_in[13];  // [L,128]
    const float* a_ff     = (const float*)d_in[14];  // [L]
    float* out = (float*)d_out;                      // [L,N,128]

    float *zP, *aggP, *hP, *hnP, *tP;
    cudaGetSymbolAddress((void**)&zP,   g_z);
    cudaGetSymbolAddress((void**)&aggP, g_agg);
    cudaGetSymbolAddress((void**)&hP,   g_h);
    cudaGetSymbolAddress((void**)&hnP,  g_hn);
    cudaGetSymbolAddress((void**)&tP,   g_t);

    const int MTILES = (NNODES + 63) / 64;           // 782
    const int EH_BLOCKS = (NEDGES * HH + 255) / 256; // 18750
    const int NH_BLOCKS = (NNODES * HH + 255) / 256; // 1563

    for (int l = 0; l < LL; l++) {
        const float* x = (l == 0) ? in_feats : (out + (size_t)(l - 1) * NNODES * DM);

        cudaMemsetAsync(aggP, 0, (size_t)NNODES * DM * sizeof(float));

        // z = x @ W[l]
        sgemm64<0><<<dim3(DM / 64, MTILES), 256>>>(
            x, W + (size_t)l * DM * DM, zP, NNODES, DM, DM,
            nullptr, nullptr, nullptr);

        // el / er + init emax/denom
        elr_kernel<<<NH_BLOCKS, 256>>>(attn_l + (size_t)l * DM,
                                       attn_r + (size_t)l * DM);

        edge_att<<<EH_BLOCKS, 256>>>(src, dst);
        edge_exp<<<EH_BLOCKS, 256>>>(dst);
        edge_scatter<<<EH_BLOCKS, 256>>>(src, dst);

        node_ln<<<NNODES, 128>>>(conv_b + (size_t)l * DM, a_conv + l,
                                 ln_scale + (size_t)l * DM,
                                 ln_bias + (size_t)l * DM);

        // t = prelu(hn @ W1[l] + b1[l])
        sgemm64<1><<<dim3(DFFH / 64, MTILES), 256>>>(
            hnP, W1 + (size_t)l * DM * DFFH, tP, NNODES, DFFH, DM,
            b1 + (size_t)l * DFFH, a_ff + l, nullptr);

        // out[l] = h + t @ W2[l] + b2[l]
        sgemm64<2><<<dim3(DM / 64, MTILES), 256>>>(
            tP, W2 + (size_t)l * DFFH * DM, out + (size_t)l * NNODES * DM,
            NNODES, DM, DFFH,
            b2 + (size_t)l * DM, nullptr, hP);
    }
}

// round 3
// speedup vs baseline: 1.8027x; 1.8027x over previous
#include <cuda_runtime.h>
#include <math.h>
#include <stdint.h>

#define NNODES 50000
#define NEDGES 600000
#define DM 128
#define HH 8
#define DH 16
#define DFFH 512
#define LL 3
#define MTILES ((NNODES + 127) / 128)   // 391

// ---------------- scratch (static device memory; no allocs allowed) --------
__device__ float g_z [(size_t)NNODES * DM];
__device__ float g_xr[(size_t)NNODES * DM];      // tf32-rounded layer input
__device__ float g_el[(size_t)NNODES * HH];
__device__ float g_er[(size_t)NNODES * HH];
__device__ float g_e [(size_t)NEDGES * HH];
__device__ float g_emax [(size_t)NNODES * HH];
__device__ float g_denom[(size_t)NNODES * HH];
__device__ float g_agg[(size_t)NNODES * DM];
__device__ float g_h  [(size_t)NNODES * DM];
__device__ float g_hn [(size_t)NNODES * DM];     // tf32-rounded
__device__ float g_t  [(size_t)NNODES * DFFH];   // tf32-rounded
__device__ float g_bt [(size_t)512 * 512];       // B^T scratch (K-major)

// ---------------- helpers ------------------------------------------------
__device__ __forceinline__ uint32_t smem_u32(const void* p) {
    uint32_t a;
    asm("{ .reg .u64 t; cvta.to.shared.u64 t, %1; cvt.u32.u64 %0, t; }" : "=r"(a) : "l"(p));
    return a;
}
__device__ __forceinline__ float round_tf32(float x) {
    uint32_t r;
    asm("cvt.rna.tf32.f32 %0, %1;" : "=r"(r) : "f"(x));
    return __uint_as_float(r);
}
__device__ __forceinline__ void cp_async16(uint32_t saddr, const void* gaddr, uint32_t sz) {
    asm volatile("cp.async.cg.shared.global [%0], [%1], 16, %2;"
                 :: "r"(saddr), "l"(gaddr), "r"(sz) : "memory");
}
__device__ __forceinline__ void mma_tf32(float* c, const uint32_t* a, const uint32_t* b) {
    asm volatile("mma.sync.aligned.m16n8k8.row.col.f32.tf32.tf32.f32 "
                 "{%0,%1,%2,%3}, {%4,%5,%6,%7}, {%8,%9}, {%0,%1,%2,%3};"
                 : "+f"(c[0]), "+f"(c[1]), "+f"(c[2]), "+f"(c[3])
                 : "r"(a[0]), "r"(a[1]), "r"(a[2]), "r"(a[3]),
                   "r"(b[0]), "r"(b[1]));
}

// ---------------- tf32 mma.sync GEMM ------------------------------------------
// C[M x NCOUT] = A[M x KTOT] @ Bt^T  (Bt stored [NCOUT x KTOT] K-major)
// MODE 0: C = acc                                  (g_z)
// MODE 1: C = round_tf32(prelu(acc + bias[col]))   (g_t)
// MODE 2: C = acc + bias[col] + addend[row,col]    (out)
#define SPITCH 20     // 16 + 4 pad floats per smem row

template <int MODE, int KTOT, int NCOUT>
__global__ void __launch_bounds__(256) gemm_mma(
    const float* __restrict__ A, const float* __restrict__ Bt,
    float* __restrict__ C,
    const float* __restrict__ bias, const float* __restrict__ slope,
    const float* __restrict__ addend)
{
    __shared__ float As[2][128 * SPITCH];
    __shared__ float Bs[2][128 * SPITCH];

    const int tid  = threadIdx.x;
    const int lane = tid & 31;
    const int wid  = tid >> 5;
    const int warpm = wid & 3;          // 4 warps along M (32 rows each)
    const int warpn = wid >> 2;         // 2 warps along N (64 cols each)
    const int rowBase = blockIdx.y * 128;
    const int colBase = blockIdx.x * 128;
    constexpr int KT = KTOT / 16;

    const uint32_t aS = smem_u32(&As[0][0]);
    const uint32_t bS = smem_u32(&Bs[0][0]);
    constexpr uint32_t BUFB = 128 * SPITCH * 4;   // bytes per buffer

    // ---- stage loader: 128x16 tile of A and Bt each ----
    auto load_stage = [&](int buf, int k0) {
        #pragma unroll
        for (int i = 0; i < 2; i++) {
            int chunk = tid + i * 256;          // 0..511 float4 chunks
            int m  = chunk >> 2;                // 0..127
            int kq = (chunk & 3) * 4;           // 0,4,8,12
            uint32_t soff = (uint32_t)(m * SPITCH + kq) * 4 + buf * BUFB;
            int gr = rowBase + m;
            const float* ga = A + (size_t)(gr < NNODES ? gr : 0) * KTOT + k0 + kq;
            cp_async16(aS + soff, ga, (gr < NNODES) ? 16u : 0u);
            const float* gb = Bt + (size_t)(colBase + m) * KTOT + k0 + kq;
            cp_async16(bS + soff, gb, 16u);
        }
    };

    float acc[2][8][4];
    #pragma unroll
    for (int ms = 0; ms < 2; ms++)
        #pragma unroll
        for (int ns = 0; ns < 8; ns++)
            #pragma unroll
            for (int q = 0; q < 4; q++) acc[ms][ns][q] = 0.0f;

    load_stage(0, 0);
    asm volatile("cp.async.commit_group;" ::: "memory");

    const int arow = warpm * 32 + (lane >> 2);
    const int bcol = warpn * 64 + (lane >> 2);
    const int kln  = lane & 3;

    #pragma unroll 1
    for (int kt = 0; kt < KT; ++kt) {
        const int buf = kt & 1;
        if (kt + 1 < KT) {
            load_stage(buf ^ 1, (kt + 1) * 16);
            asm volatile("cp.async.commit_group;" ::: "memory");
            asm volatile("cp.async.wait_group 1;" ::: "memory");
        } else {
            asm volatile("cp.async.wait_group 0;" ::: "memory");
        }
        __syncthreads();

        const float* Ab = As[buf];
        const float* Bb = Bs[buf];
        #pragma unroll
        for (int sub = 0; sub < 2; sub++) {
            const int kb = sub * 8 + kln;
            uint32_t a[2][4], b[8][2];
            #pragma unroll
            for (int ms = 0; ms < 2; ms++) {
                int r = arow + ms * 16;
                a[ms][0] = __float_as_uint(Ab[r * SPITCH + kb]);
                a[ms][1] = __float_as_uint(Ab[(r + 8) * SPITCH + kb]);
                a[ms][2] = __float_as_uint(Ab[r * SPITCH + kb + 4]);
                a[ms][3] = __float_as_uint(Ab[(r + 8) * SPITCH + kb + 4]);
            }
            #pragma unroll
            for (int ns = 0; ns < 8; ns++) {
                int cco = (bcol + ns * 8) * SPITCH;
                b[ns][0] = __float_as_uint(Bb[cco + sub * 8 + kln]);
                b[ns][1] = __float_as_uint(Bb[cco + sub * 8 + kln + 4]);
            }
            #pragma unroll
            for (int ms = 0; ms < 2; ms++)
                #pragma unroll
                for (int ns = 0; ns < 8; ns++)
                    mma_tf32(acc[ms][ns], a[ms], b[ns]);
        }
        __syncthreads();
    }

    // ---------------- epilogue ----------------
    float slp = 0.0f;
    if (MODE == 1) slp = __ldg(slope);

    #pragma unroll
    for (int ms = 0; ms < 2; ms++) {
        int r0 = rowBase + warpm * 32 + ms * 16 + (lane >> 2);
        #pragma unroll
        for (int half = 0; half < 2; half++) {
            int r = r0 + half * 8;
            if (r >= NNODES) continue;
            #pragma unroll
            for (int ns = 0; ns < 8; ns++) {
                int c = colBase + warpn * 64 + ns * 8 + (lane & 3) * 2;
                float v0 = acc[ms][ns][half * 2 + 0];
                float v1 = acc[ms][ns][half * 2 + 1];
                if (MODE == 0) {
                    *(float2*)&C[(size_t)r * NCOUT + c] = make_float2(v0, v1);
                } else if (MODE == 1) {
                    v0 += __ldg(bias + c);
                    v1 += __ldg(bias + c + 1);
                    v0 = (v0 >= 0.0f) ? v0 : slp * v0;
                    v1 = (v1 >= 0.0f) ? v1 : slp * v1;
                    *(float2*)&C[(size_t)r * NCOUT + c] =
                        make_float2(round_tf32(v0), round_tf32(v1));
                } else {
                    float2 hv = *(const float2*)&addend[(size_t)r * NCOUT + c];
                    v0 += __ldg(bias + c)     + hv.x;
                    v1 += __ldg(bias + c + 1) + hv.y;
                    *(float2*)&C[(size_t)r * NCOUT + c] = make_float2(v0, v1);
                }
            }
        }
    }
}

// ---------------- transpose + tf32-round: out[n*K+k] = rnd(in[k*N+n]) --------
__global__ void transpose_rnd(const float* __restrict__ in, float* __restrict__ out,
                              int K, int N)
{
    __shared__ float tile[32][33];
    int k0 = blockIdx.x * 32, n0 = blockIdx.y * 32;
    int tx = threadIdx.x, ty = threadIdx.y;
    #pragma unroll
    for (int i = 0; i < 4; i++)
        tile[ty + i * 8][tx] = in[(size_t)(k0 + ty + i * 8) * N + n0 + tx];
    __syncthreads();
    #pragma unroll
    for (int i = 0; i < 4; i++)
        out[(size_t)(n0 + ty + i * 8) * K + k0 + tx] = round_tf32(tile[tx][ty + i * 8]);
}

// ---------------- round-copy layer input -------------------------------------
__global__ void round_copy(const float* __restrict__ in, float* __restrict__ out, int n4)
{
    int i = blockIdx.x * blockDim.x + threadIdx.x;
    if (i >= n4) return;
    float4 v = ((const float4*)in)[i];
    v.x = round_tf32(v.x); v.y = round_tf32(v.y);
    v.z = round_tf32(v.z); v.w = round_tf32(v.w);
    ((float4*)out)[i] = v;
}

// ---------------- per-node attention coefficients + init ---------------------
__global__ void elr_kernel(const float* __restrict__ attn_l,
                           const float* __restrict__ attn_r)
{
    int idx = blockIdx.x * blockDim.x + threadIdx.x;
    if (idx >= NNODES * HH) return;
    int n = idx >> 3, h = idx & 7;
    const float* zp = g_z + (size_t)n * DM + h * DH;
    float sl = 0.f, sr = 0.f;
    #pragma unroll
    for (int d = 0; d < DH; d++) {
        float zv = zp[d];
        sl += zv * attn_l[h * DH + d];
        sr += zv * attn_r[h * DH + d];
    }
    g_el[idx] = sl;
    g_er[idx] = sr;
    g_emax[idx]  = -INFINITY;
    g_denom[idx] = 0.0f;
    float4* ap = (float4*)(g_agg + (size_t)n * DM + h * DH);
    #pragma unroll
    for (int q = 0; q < 4; q++) ap[q] = make_float4(0.f, 0.f, 0.f, 0.f);
}

// ---------------- edge kernels -----------------------------------------------
__device__ __forceinline__ void atomicMaxFloat(float* addr, float value) {
    unsigned int* ua = (unsigned int*)addr;
    unsigned int old = *ua;
    while (__uint_as_float(old) < value) {
        unsigned int assumed = old;
        old = atomicCAS(ua, assumed, __float_as_uint(value));
        if (old == assumed) break;
    }
}

__global__ void edge_att(const int* __restrict__ src, const int* __restrict__ dst)
{
    int idx = blockIdx.x * blockDim.x + threadIdx.x;
    if (idx >= NEDGES * HH) return;
    int e = idx >> 3, h = idx & 7;
    int s = src[e], d = dst[e];
    float v = g_el[s * HH + h] + g_er[d * HH + h];
    v = (v >= 0.0f) ? v : 0.2f * v;
    g_e[idx] = v;
    atomicMaxFloat(&g_emax[d * HH + h], v);
}

__global__ void edge_exp(const int* __restrict__ dst)
{
    int idx = blockIdx.x * blockDim.x + threadIdx.x;
    if (idx >= NEDGES * HH) return;
    int e = idx >> 3, h = idx & 7;
    int d = dst[e];
    float m = g_emax[d * HH + h];
    float ex = expf(g_e[idx] - m);
    g_e[idx] = ex;
    atomicAdd(&g_denom[d * HH + h], ex);
}

__global__ void edge_scatter(const int* __restrict__ src, const int* __restrict__ dst)
{
    int idx = blockIdx.x * blockDim.x + threadIdx.x;
    if (idx >= NEDGES * HH) return;
    int e = idx >> 3, h = idx & 7;
    int s = src[e], d = dst[e];
    float ex = g_e[idx];
    const float4* zp = (const float4*)(g_z + (size_t)s * DM + h * DH);
    float* ap = g_agg + (size_t)d * DM + h * DH;
    #pragma unroll
    for (int q = 0; q < 4; q++) {
        float4 zv = zp[q];
        float x = ex * zv.x, y = ex * zv.y, zz = ex * zv.z, w = ex * zv.w;
        asm volatile("red.global.add.v4.f32 [%0], {%1, %2, %3, %4};"
                     :: "l"(ap + q * 4), "f"(x), "f"(y), "f"(zz), "f"(w)
                     : "memory");
    }
}

// ---------------- normalize + PReLU + 2x LayerNorm ---------------------------
__device__ __forceinline__ void blockReduce2_128(float& a, float& b, float* sm) {
    __syncthreads();
    #pragma unroll
    for (int o = 16; o > 0; o >>= 1) {
        a += __shfl_down_sync(0xFFFFFFFFu, a, o);
        b += __shfl_down_sync(0xFFFFFFFFu, b, o);
    }
    int w = threadIdx.x >> 5, lane = threadIdx.x & 31;
    if (lane == 0) { sm[w] = a; sm[4 + w] = b; }
    __syncthreads();
    if (threadIdx.x < 32) {
        a = (lane < 4) ? sm[lane] : 0.0f;
        b = (lane < 4) ? sm[4 + lane] : 0.0f;
        #pragma unroll
        for (int o = 2; o > 0; o >>= 1) {
            a += __shfl_down_sync(0xFFFFFFFFu, a, o);
            b += __shfl_down_sync(0xFFFFFFFFu, b, o);
        }
        if (lane == 0) { sm[0] = a; sm[1] = b; }
    }
    __syncthreads();
    a = sm[0];
    b = sm[1];
}

__global__ void __launch_bounds__(128) node_ln(
    const float* __restrict__ conv_bias, const float* __restrict__ a_conv,
    const float* __restrict__ ln_scale,  const float* __restrict__ ln_bias)
{
    __shared__ float sm[8];
    int n = blockIdx.x;
    int c = threadIdx.x;
    int h = c >> 4;

    float den = fmaxf(g_denom[n * HH + h], 1e-9f);
    float v = g_agg[(size_t)n * DM + c] / den + conv_bias[c];
    float a = *a_conv;
    v = (v >= 0.0f) ? v : a * v;

    float s = v, s2 = v * v;
    blockReduce2_128(s, s2, sm);
    float m = s * (1.0f / DM);
    float var = s2 * (1.0f / DM) - m * m;
    float hv = (v - m) * rsqrtf(var + 1e-5f) * ln_scale[c] + ln_bias[c];
    g_h[(size_t)n * DM + c] = hv;

    float t = hv, t2 = hv * hv;
    blockReduce2_128(t, t2, sm);
    float m2 = t * (1.0f / DM);
    float var2 = t2 * (1.0f / DM) - m2 * m2;
    float hn = (hv - m2) * rsqrtf(var2 + 1e-5f) * ln_scale[c] + ln_bias[c];
    g_hn[(size_t)n * DM + c] = round_tf32(hn);
}

// ---------------- launcher ---------------------------------------------------
extern "C" void kernel_launch(void* const* d_in, const int* in_sizes, int n_in,
                              void* d_out, int out_size)
{
    const float* in_feats = (const float*)d_in[0];
    const int*   src      = (const int*)  d_in[1];
    const int*   dst      = (const int*)  d_in[2];
    const float* W        = (const float*)d_in[3];
    const float* attn_l   = (const float*)d_in[4];
    const float* attn_r   = (const float*)d_in[5];
    const float* conv_b   = (const float*)d_in[6];
    const float* a_conv   = (const float*)d_in[7];
    const float* ln_scale = (const float*)d_in[8];
    const float* ln_bias  = (const float*)d_in[9];
    const float* W1       = (const float*)d_in[10];
    const float* b1       = (const float*)d_in[11];
    const float* W2       = (const float*)d_in[12];
    const float* b2       = (const float*)d_in[13];
    const float* a_ff     = (const float*)d_in[14];
    float* out = (float*)d_out;

    float *zP, *xrP, *hP, *hnP, *tP, *btP;
    cudaGetSymbolAddress((void**)&zP,  g_z);
    cudaGetSymbolAddress((void**)&xrP, g_xr);
    cudaGetSymbolAddress((void**)&hP,  g_h);
    cudaGetSymbolAddress((void**)&hnP, g_hn);
    cudaGetSymbolAddress((void**)&tP,  g_t);
    cudaGetSymbolAddress((void**)&btP, g_bt);

    const int EH_BLOCKS = (NEDGES * HH + 255) / 256;
    const int NH_BLOCKS = (NNODES * HH + 255) / 256;
    const int RC_BLOCKS = (NNODES * DM / 4 + 255) / 256;

    for (int l = 0; l < LL; l++) {
        const float* x = (l == 0) ? in_feats : (out + (size_t)(l - 1) * NNODES * DM);

        round_copy<<<RC_BLOCKS, 256>>>(x, xrP, NNODES * DM / 4);

        // Bt = round(W^T) [128,128]
        transpose_rnd<<<dim3(DM / 32, DM / 32), dim3(32, 8)>>>(
            W + (size_t)l * DM * DM, btP, DM, DM);

        // z = xr @ W
        gemm_mma<0, 128, 128><<<dim3(1, MTILES), 256>>>(
            xrP, btP, zP, nullptr, nullptr, nullptr);

        elr_kernel<<<NH_BLOCKS, 256>>>(attn_l + (size_t)l * DM,
                                       attn_r + (size_t)l * DM);

        edge_att<<<EH_BLOCKS, 256>>>(src, dst);
        edge_exp<<<EH_BLOCKS, 256>>>(dst);
        edge_scatter<<<EH_BLOCKS, 256>>>(src, dst);

        node_ln<<<NNODES, 128>>>(conv_b + (size_t)l * DM, a_conv + l,
                                 ln_scale + (size_t)l * DM,
                                 ln_bias + (size_t)l * DM);

        // Bt = round(W1^T) [512,128]
        transpose_rnd<<<dim3(DM / 32, DFFH / 32), dim3(32, 8)>>>(
            W1 + (size_t)l * DM * DFFH, btP, DM, DFFH);

        // t = round(prelu(hn @ W1 + b1))
        gemm_mma<1, 128, 512><<<dim3(DFFH / 128, MTILES), 256>>>(
            hnP, btP, tP, b1 + (size_t)l * DFFH, a_ff + l, nullptr);

        // Bt = round(W2^T) [128,512]
        transpose_rnd<<<dim3(DFFH / 32, DM / 32), dim3(32, 8)>>>(
            W2 + (size_t)l * DFFH * DM, btP, DFFH, DM);

        // out[l] = h + t @ W2 + b2
        gemm_mma<2, 512, 128><<<dim3(1, MTILES), 256>>>(
            tP, btP, out + (size_t)l * NNODES * DM,
            b2 + (size_t)l * DM, nullptr, hP);
    }
}

// round 4
// speedup vs baseline: 2.3223x; 1.2883x over previous
#include <cuda_runtime.h>
#include <math.h>
#include <stdint.h>

#define NNODES 50000
#define NEDGES 600000
#define DM 128
#define HH 8
#define DH 16
#define DFFH 512
#define LL 3
#define MTILES ((NNODES + 127) / 128)   // 391

// ---------------- scratch (static device memory; no allocs allowed) --------
__device__ float g_z [(size_t)NNODES * DM];
__device__ float g_xr[(size_t)NNODES * DM];      // tf32-rounded layer input
__device__ float g_el[(size_t)NNODES * HH];
__device__ float g_er[(size_t)NNODES * HH];
__device__ float g_denom[(size_t)NNODES * HH];
__device__ float g_agg[(size_t)NNODES * DM];
__device__ float g_h  [(size_t)NNODES * DM];
__device__ float g_hn [(size_t)NNODES * DM];     // tf32-rounded
__device__ float g_t  [(size_t)NNODES * DFFH];   // tf32-rounded
__device__ float g_bt [(size_t)3 * (DM * DM + DM * DFFH + DFFH * DM)]; // all W^T

#define OFF_W(l)  ((size_t)(l) * DM * DM)
#define OFF_W1(l) ((size_t)3 * DM * DM + (size_t)(l) * DM * DFFH)
#define OFF_W2(l) ((size_t)3 * DM * DM + (size_t)3 * DM * DFFH + (size_t)(l) * DFFH * DM)

// ---------------- helpers ------------------------------------------------
__device__ __forceinline__ uint32_t smem_u32(const void* p) {
    uint32_t a;
    asm("{ .reg .u64 t; cvta.to.shared.u64 t, %1; cvt.u32.u64 %0, t; }" : "=r"(a) : "l"(p));
    return a;
}
__device__ __forceinline__ float round_tf32(float x) {
    uint32_t r;
    asm("cvt.rna.tf32.f32 %0, %1;" : "=r"(r) : "f"(x));
    return __uint_as_float(r);
}
__device__ __forceinline__ void cp_async16(uint32_t saddr, const void* gaddr, uint32_t sz) {
    asm volatile("cp.async.cg.shared.global [%0], [%1], 16, %2;"
                 :: "r"(saddr), "l"(gaddr), "r"(sz) : "memory");
}
__device__ __forceinline__ void mma_tf32(float* c, const uint32_t* a, const uint32_t* b) {
    asm volatile("mma.sync.aligned.m16n8k8.row.col.f32.tf32.tf32.f32 "
                 "{%0,%1,%2,%3}, {%4,%5,%6,%7}, {%8,%9}, {%0,%1,%2,%3};"
                 : "+f"(c[0]), "+f"(c[1]), "+f"(c[2]), "+f"(c[3])
                 : "r"(a[0]), "r"(a[1]), "r"(a[2]), "r"(a[3]),
                   "r"(b[0]), "r"(b[1]));
}

// ---------------- tf32 mma.sync GEMM ------------------------------------------
// C[M x NCOUT] = A[M x KTOT] @ Bt^T  (Bt stored [NCOUT x KTOT] K-major)
// MODE 0: C = acc -> g_z; fused el/er epilogue; denom=0; agg=0
// MODE 1: C = round_tf32(prelu(acc + bias[col]))   (g_t)
// MODE 2: C = acc + bias[col] + addend[row,col]; also g_xr = round(C)
#define SPITCH 20     // 16 + 4 pad floats per smem row

template <int MODE, int KTOT, int NCOUT>
__global__ void __launch_bounds__(256) gemm_mma(
    const float* __restrict__ A, const float* __restrict__ Bt,
    float* __restrict__ C,
    const float* __restrict__ bias, const float* __restrict__ slope,
    const float* __restrict__ addend,
    const float* __restrict__ attn_l, const float* __restrict__ attn_r)
{
    __shared__ float As[2][128 * SPITCH];
    __shared__ float Bs[2][128 * SPITCH];
    __shared__ float sAL[DM], sAR[DM];

    const int tid  = threadIdx.x;
    const int lane = tid & 31;
    const int wid  = tid >> 5;
    const int warpm = wid & 3;          // 4 warps along M (32 rows each)
    const int warpn = wid >> 2;         // 2 warps along N (64 cols each)
    const int rowBase = blockIdx.y * 128;
    const int colBase = blockIdx.x * 128;
    constexpr int KT = KTOT / 16;

    if (MODE == 0 && tid < DM) { sAL[tid] = attn_l[tid]; sAR[tid] = attn_r[tid]; }

    const uint32_t aS = smem_u32(&As[0][0]);
    const uint32_t bS = smem_u32(&Bs[0][0]);
    constexpr uint32_t BUFB = 128 * SPITCH * 4;   // bytes per buffer

    auto load_stage = [&](int buf, int k0) {
        #pragma unroll
        for (int i = 0; i < 2; i++) {
            int chunk = tid + i * 256;          // 0..511 float4 chunks
            int m  = chunk >> 2;                // 0..127
            int kq = (chunk & 3) * 4;           // 0,4,8,12
            uint32_t soff = (uint32_t)(m * SPITCH + kq) * 4 + buf * BUFB;
            int gr = rowBase + m;
            const float* ga = A + (size_t)(gr < NNODES ? gr : 0) * KTOT + k0 + kq;
            cp_async16(aS + soff, ga, (gr < NNODES) ? 16u : 0u);
            const float* gb = Bt + (size_t)(colBase + m) * KTOT + k0 + kq;
            cp_async16(bS + soff, gb, 16u);
        }
    };

    float acc[2][8][4];
    #pragma unroll
    for (int ms = 0; ms < 2; ms++)
        #pragma unroll
        for (int ns = 0; ns < 8; ns++)
            #pragma unroll
            for (int q = 0; q < 4; q++) acc[ms][ns][q] = 0.0f;

    load_stage(0, 0);
    asm volatile("cp.async.commit_group;" ::: "memory");

    const int arow = warpm * 32 + (lane >> 2);
    const int bcol = warpn * 64 + (lane >> 2);
    const int kln  = lane & 3;

    #pragma unroll 2
    for (int kt = 0; kt < KT; ++kt) {
        const int buf = kt & 1;
        if (kt + 1 < KT) {
            load_stage(buf ^ 1, (kt + 1) * 16);
            asm volatile("cp.async.commit_group;" ::: "memory");
            asm volatile("cp.async.wait_group 1;" ::: "memory");
        } else {
            asm volatile("cp.async.wait_group 0;" ::: "memory");
        }
        __syncthreads();

        const float* Ab = As[buf];
        const float* Bb = Bs[buf];
        #pragma unroll
        for (int sub = 0; sub < 2; sub++) {
            const int kb = sub * 8 + kln;
            uint32_t a[2][4], b[8][2];
            #pragma unroll
            for (int ms = 0; ms < 2; ms++) {
                int r = arow + ms * 16;
                a[ms][0] = __float_as_uint(Ab[r * SPITCH + kb]);
                a[ms][1] = __float_as_uint(Ab[(r + 8) * SPITCH + kb]);
                a[ms][2] = __float_as_uint(Ab[r * SPITCH + kb + 4]);
                a[ms][3] = __float_as_uint(Ab[(r + 8) * SPITCH + kb + 4]);
            }
            #pragma unroll
            for (int ns = 0; ns < 8; ns++) {
                int cco = (bcol + ns * 8) * SPITCH;
                b[ns][0] = __float_as_uint(Bb[cco + sub * 8 + kln]);
                b[ns][1] = __float_as_uint(Bb[cco + sub * 8 + kln + 4]);
            }
            #pragma unroll
            for (int ms = 0; ms < 2; ms++)
                #pragma unroll
                for (int ns = 0; ns < 8; ns++)
                    mma_tf32(acc[ms][ns], a[ms], b[ns]);
        }
        __syncthreads();
    }

    // ---------------- epilogue ----------------
    float slp = 0.0f;
    if (MODE == 1) slp = __ldg(slope);

    #pragma unroll
    for (int ms = 0; ms < 2; ms++) {
        #pragma unroll
        for (int half = 0; half < 2; half++) {
            int r = rowBase + warpm * 32 + ms * 16 + half * 8 + (lane >> 2);
            const bool valid = (r < NNODES);
            float psl[4], psr[4];
            if (MODE == 0) {
                #pragma unroll
                for (int q = 0; q < 4; q++) { psl[q] = 0.f; psr[q] = 0.f; }
            }
            #pragma unroll
            for (int ns = 0; ns < 8; ns++) {
                int cl = warpn * 64 + ns * 8 + (lane & 3) * 2;  // local col
                int c = colBase + cl;
                float v0 = acc[ms][ns][half * 2 + 0];
                float v1 = acc[ms][ns][half * 2 + 1];
                if (MODE == 0) {
                    if (valid) {
                        *(float2*)&C[(size_t)r * NCOUT + c] = make_float2(v0, v1);
                        *(float2*)&g_agg[(size_t)r * DM + c] = make_float2(0.f, 0.f);
                    }
                    int hh = ns >> 1;
                    psl[hh] += v0 * sAL[cl] + v1 * sAL[cl + 1];
                    psr[hh] += v0 * sAR[cl] + v1 * sAR[cl + 1];
                } else if (MODE == 1) {
                    if (valid) {
                        v0 += __ldg(bias + c);
                        v1 += __ldg(bias + c + 1);
                        v0 = (v0 >= 0.0f) ? v0 : slp * v0;
                        v1 = (v1 >= 0.0f) ? v1 : slp * v1;
                        *(float2*)&C[(size_t)r * NCOUT + c] =
                            make_float2(round_tf32(v0), round_tf32(v1));
                    }
                } else {
                    if (valid) {
                        float2 hv = *(const float2*)&addend[(size_t)r * NCOUT + c];
                        v0 += __ldg(bias + c)     + hv.x;
                        v1 += __ldg(bias + c + 1) + hv.y;
                        *(float2*)&C[(size_t)r * NCOUT + c] = make_float2(v0, v1);
                        *(float2*)&g_xr[(size_t)r * DM + c] =
                            make_float2(round_tf32(v0), round_tf32(v1));
                    }
                }
            }
            if (MODE == 0) {
                #pragma unroll
                for (int d = 1; d <= 2; d <<= 1) {
                    #pragma unroll
                    for (int q = 0; q < 4; q++) {
                        psl[q] += __shfl_xor_sync(0xFFFFFFFFu, psl[q], d);
                        psr[q] += __shfl_xor_sync(0xFFFFFFFFu, psr[q], d);
                    }
                }
                if ((lane & 3) == 0 && valid) {
                    #pragma unroll
                    for (int q = 0; q < 4; q++) {
                        int hidx = r * HH + warpn * 4 + q;
                        g_el[hidx] = psl[q];
                        g_er[hidx] = psr[q];
                        g_denom[hidx] = 0.0f;
                    }
                }
            }
        }
    }
}

// ---------------- transpose + tf32-round: out[n*K+k] = rnd(in[k*N+n]) --------
__global__ void transpose_rnd(const float* __restrict__ in, float* __restrict__ out,
                              int K, int N)
{
    __shared__ float tile[32][33];
    int k0 = blockIdx.x * 32, n0 = blockIdx.y * 32;
    int tx = threadIdx.x, ty = threadIdx.y;
    #pragma unroll
    for (int i = 0; i < 4; i++)
        tile[ty + i * 8][tx] = in[(size_t)(k0 + ty + i * 8) * N + n0 + tx];
    __syncthreads();
    #pragma unroll
    for (int i = 0; i < 4; i++)
        out[(size_t)(n0 + ty + i * 8) * K + k0 + tx] = round_tf32(tile[tx][ty + i * 8]);
}

// ---------------- round-copy layer-0 input -----------------------------------
__global__ void round_copy(const float* __restrict__ in, float* __restrict__ out, int n4)
{
    int i = blockIdx.x * blockDim.x + threadIdx.x;
    if (i >= n4) return;
    float4 v = ((const float4*)in)[i];
    v.x = round_tf32(v.x); v.y = round_tf32(v.y);
    v.z = round_tf32(v.z); v.w = round_tf32(v.w);
    ((float4*)out)[i] = v;
}

// ---------------- fused edge pass: logits -> exp -> denom + scatter ----------
// No max-subtraction: softmax is shift-invariant and logits are O(1), so
// exp() cannot overflow fp32; result identical to reference up to rounding.
__global__ void edge_fused(const int* __restrict__ src, const int* __restrict__ dst)
{
    int idx = blockIdx.x * blockDim.x + threadIdx.x;
    if (idx >= NEDGES * HH) return;
    int e = idx >> 3, h = idx & 7;
    int s = src[e], d = dst[e];
    float v = g_el[s * HH + h] + g_er[d * HH + h];
    v = (v >= 0.0f) ? v : 0.2f * v;
    float ex = __expf(v);
    asm volatile("red.global.add.f32 [%0], %1;"
                 :: "l"(g_denom + d * HH + h), "f"(ex) : "memory");
    const float4* zp = (const float4*)(g_z + (size_t)s * DM + h * DH);
    float* ap = g_agg + (size_t)d * DM + h * DH;
    #pragma unroll
    for (int q = 0; q < 4; q++) {
        float4 zv = zp[q];
        float x = ex * zv.x, y = ex * zv.y, zz = ex * zv.z, w = ex * zv.w;
        asm volatile("red.global.add.v4.f32 [%0], {%1, %2, %3, %4};"
                     :: "l"(ap + q * 4), "f"(x), "f"(y), "f"(zz), "f"(w)
                     : "memory");
    }
}

// ---------------- normalize + PReLU + 2x LayerNorm (warp per node) -----------
__global__ void __launch_bounds__(256) node_ln(
    const float* __restrict__ conv_bias, const float* __restrict__ a_conv,
    const float* __restrict__ ln_scale,  const float* __restrict__ ln_bias)
{
    int n = blockIdx.x * 8 + (threadIdx.x >> 5);
    if (n >= NNODES) return;
    int lane = threadIdx.x & 31;
    int c = lane * 4;
    int h = lane >> 2;

    float den = fmaxf(g_denom[n * HH + h], 1e-9f);
    float4 v4 = *(const float4*)&g_agg[(size_t)n * DM + c];
    float4 cb = *(const float4*)&conv_bias[c];
    float a = __ldg(a_conv);
    float v[4] = {v4.x / den + cb.x, v4.y / den + cb.y,
                  v4.z / den + cb.z, v4.w / den + cb.w};
    #pragma unroll
    for (int q = 0; q < 4; q++) v[q] = (v[q] >= 0.0f) ? v[q] : a * v[q];

    float s = 0.f, s2 = 0.f;
    #pragma unroll
    for (int q = 0; q < 4; q++) { s += v[q]; s2 += v[q] * v[q]; }
    #pragma unroll
    for (int o = 16; o > 0; o >>= 1) {
        s  += __shfl_xor_sync(0xFFFFFFFFu, s, o);
        s2 += __shfl_xor_sync(0xFFFFFFFFu, s2, o);
    }
    float m = s * (1.0f / DM);
    float var = s2 * (1.0f / DM) - m * m;
    float inv = rsqrtf(var + 1e-5f);
    float4 lsc = *(const float4*)&ln_scale[c];
    float4 lbi = *(const float4*)&ln_bias[c];
    float hv[4];
    hv[0] = (v[0] - m) * inv * lsc.x + lbi.x;
    hv[1] = (v[1] - m) * inv * lsc.y + lbi.y;
    hv[2] = (v[2] - m) * inv * lsc.z + lbi.z;
    hv[3] = (v[3] - m) * inv * lsc.w + lbi.w;
    *(float4*)&g_h[(size_t)n * DM + c] = make_float4(hv[0], hv[1], hv[2], hv[3]);

    float t = 0.f, t2 = 0.f;
    #pragma unroll
    for (int q = 0; q < 4; q++) { t += hv[q]; t2 += hv[q] * hv[q]; }
    #pragma unroll
    for (int o = 16; o > 0; o >>= 1) {
        t  += __shfl_xor_sync(0xFFFFFFFFu, t, o);
        t2 += __shfl_xor_sync(0xFFFFFFFFu, t2, o);
    }
    float m2 = t * (1.0f / DM);
    float var2 = t2 * (1.0f / DM) - m2 * m2;
    float inv2 = rsqrtf(var2 + 1e-5f);
    float4 o4;
    o4.x = round_tf32((hv[0] - m2) * inv2 * lsc.x + lbi.x);
    o4.y = round_tf32((hv[1] - m2) * inv2 * lsc.y + lbi.y);
    o4.z = round_tf32((hv[2] - m2) * inv2 * lsc.z + lbi.z);
    o4.w = round_tf32((hv[3] - m2) * inv2 * lsc.w + lbi.w);
    *(float4*)&g_hn[(size_t)n * DM + c] = o4;
}

// ---------------- launcher ---------------------------------------------------
extern "C" void kernel_launch(void* const* d_in, const int* in_sizes, int n_in,
                              void* d_out, int out_size)
{
    const float* in_feats = (const float*)d_in[0];
    const int*   src      = (const int*)  d_in[1];
    const int*   dst      = (const int*)  d_in[2];
    const float* W        = (const float*)d_in[3];
    const float* attn_l   = (const float*)d_in[4];
    const float* attn_r   = (const float*)d_in[5];
    const float* conv_b   = (const float*)d_in[6];
    const float* a_conv   = (const float*)d_in[7];
    const float* ln_scale = (const float*)d_in[8];
    const float* ln_bias  = (const float*)d_in[9];
    const float* W1       = (const float*)d_in[10];
    const float* b1       = (const float*)d_in[11];
    const float* W2       = (const float*)d_in[12];
    const float* b2       = (const float*)d_in[13];
    const float* a_ff     = (const float*)d_in[14];
    float* out = (float*)d_out;

    float *zP, *xrP, *hP, *hnP, *tP, *btP;
    cudaGetSymbolAddress((void**)&zP,  g_z);
    cudaGetSymbolAddress((void**)&xrP, g_xr);
    cudaGetSymbolAddress((void**)&hP,  g_h);
    cudaGetSymbolAddress((void**)&hnP, g_hn);
    cudaGetSymbolAddress((void**)&tP,  g_t);
    cudaGetSymbolAddress((void**)&btP, g_bt);

    const int EH_BLOCKS = (NEDGES * HH + 255) / 256;
    const int RC_BLOCKS = (NNODES * DM / 4 + 255) / 256;

    // hoist all weight transposes (independent of layer dataflow)
    for (int l = 0; l < LL; l++) {
        transpose_rnd<<<dim3(DM / 32, DM / 32), dim3(32, 8)>>>(
            W + (size_t)l * DM * DM, btP + OFF_W(l), DM, DM);
        transpose_rnd<<<dim3(DM / 32, DFFH / 32), dim3(32, 8)>>>(
            W1 + (size_t)l * DM * DFFH, btP + OFF_W1(l), DM, DFFH);
        transpose_rnd<<<dim3(DFFH / 32, DM / 32), dim3(32, 8)>>>(
            W2 + (size_t)l * DFFH * DM, btP + OFF_W2(l), DFFH, DM);
    }
    round_copy<<<RC_BLOCKS, 256>>>(in_feats, xrP, NNODES * DM / 4);

    for (int l = 0; l < LL; l++) {
        // z = xr @ W  (+ fused el/er + denom/agg init)
        gemm_mma<0, 128, 128><<<dim3(1, MTILES), 256>>>(
            xrP, btP + OFF_W(l), zP, nullptr, nullptr, nullptr,
            attn_l + (size_t)l * DM, attn_r + (size_t)l * DM);

        edge_fused<<<EH_BLOCKS, 256>>>(src, dst);

        node_ln<<<(NNODES + 7) / 8, 256>>>(conv_b + (size_t)l * DM, a_conv + l,
                                           ln_scale + (size_t)l * DM,
                                           ln_bias + (size_t)l * DM);

        // t = round(prelu(hn @ W1 + b1))
        gemm_mma<1, 128, 512><<<dim3(DFFH / 128, MTILES), 256>>>(
            hnP, btP + OFF_W1(l), tP, b1 + (size_t)l * DFFH, a_ff + l, nullptr,
            nullptr, nullptr);

        // out[l] = h + t @ W2 + b2; g_xr = round(out[l])
        gemm_mma<2, 512, 128><<<dim3(1, MTILES), 256>>>(
            tP, btP + OFF_W2(l), out + (size_t)l * NNODES * DM,
            b2 + (size_t)l * DM, nullptr, hP,
            nullptr, nullptr);
    }
}

// round 5
// speedup vs baseline: 2.7859x; 1.1996x over previous
#include <cuda_runtime.h>
#include <math.h>
#include <stdint.h>

#define NNODES 50000
#define NEDGES 600000
#define DM 128
#define HH 8
#define DH 16
#define DFFH 512
#define LL 3
#define MTILES ((NNODES + 127) / 128)   // 391

// ---------------- scratch (static device memory; no allocs allowed) --------
__device__ float g_z [(size_t)NNODES * DM];
__device__ float g_xr[(size_t)NNODES * DM];      // tf32-rounded layer input
__device__ float g_el[(size_t)NNODES * HH];
__device__ float g_er[(size_t)NNODES * HH];
__device__ float g_h  [(size_t)NNODES * DM];
__device__ float g_hn [(size_t)NNODES * DM];     // tf32-rounded
__device__ float g_t  [(size_t)NNODES * DFFH];   // tf32-rounded
__device__ float g_bt [(size_t)3 * (DM * DM + DM * DFFH + DFFH * DM)]; // all W^T
__device__ int   g_cnt[NNODES + 1];              // counts -> rowptr
__device__ int   g_wo [NNODES];                  // scatter write offsets
__device__ int   g_adj[NEDGES];                  // src ids grouped by dst

#define OFF_W(l)  ((size_t)(l) * DM * DM)
#define OFF_W1(l) ((size_t)3 * DM * DM + (size_t)(l) * DM * DFFH)
#define OFF_W2(l) ((size_t)3 * DM * DM + (size_t)3 * DM * DFFH + (size_t)(l) * DFFH * DM)

// ---------------- helpers ------------------------------------------------
__device__ __forceinline__ uint32_t smem_u32(const void* p) {
    uint32_t a;
    asm("{ .reg .u64 t; cvta.to.shared.u64 t, %1; cvt.u32.u64 %0, t; }" : "=r"(a) : "l"(p));
    return a;
}
__device__ __forceinline__ float round_tf32(float x) {
    uint32_t r;
    asm("cvt.rna.tf32.f32 %0, %1;" : "=r"(r) : "f"(x));
    return __uint_as_float(r);
}
__device__ __forceinline__ void cp_async16(uint32_t saddr, const void* gaddr, uint32_t sz) {
    asm volatile("cp.async.cg.shared.global [%0], [%1], 16, %2;"
                 :: "r"(saddr), "l"(gaddr), "r"(sz) : "memory");
}
__device__ __forceinline__ void mma_tf32(float* c, const uint32_t* a, const uint32_t* b) {
    asm volatile("mma.sync.aligned.m16n8k8.row.col.f32.tf32.tf32.f32 "
                 "{%0,%1,%2,%3}, {%4,%5,%6,%7}, {%8,%9}, {%0,%1,%2,%3};"
                 : "+f"(c[0]), "+f"(c[1]), "+f"(c[2]), "+f"(c[3])
                 : "r"(a[0]), "r"(a[1]), "r"(a[2]), "r"(a[3]),
                   "r"(b[0]), "r"(b[1]));
}

// ---------------- tf32 mma.sync GEMM ------------------------------------------
// C[M x NCOUT] = A[M x KTOT] @ Bt^T  (Bt stored [NCOUT x KTOT] K-major)
// MODE 0: C = acc -> g_z; fused el/er epilogue
// MODE 1: C = round_tf32(prelu(acc + bias[col]))   (g_t)
// MODE 2: C = acc + bias[col] + addend[row,col]; also g_xr = round(C)
#define SPITCH 20     // 16 + 4 pad floats per smem row

template <int MODE, int KTOT, int NCOUT>
__global__ void __launch_bounds__(256) gemm_mma(
    const float* __restrict__ A, const float* __restrict__ Bt,
    float* __restrict__ C,
    const float* __restrict__ bias, const float* __restrict__ slope,
    const float* __restrict__ addend,
    const float* __restrict__ attn_l, const float* __restrict__ attn_r)
{
    __shared__ float As[2][128 * SPITCH];
    __shared__ float Bs[2][128 * SPITCH];
    __shared__ float sAL[DM], sAR[DM];

    const int tid  = threadIdx.x;
    const int lane = tid & 31;
    const int wid  = tid >> 5;
    const int warpm = wid & 3;          // 4 warps along M (32 rows each)
    const int warpn = wid >> 2;         // 2 warps along N (64 cols each)
    const int rowBase = blockIdx.y * 128;
    const int colBase = blockIdx.x * 128;
    constexpr int KT = KTOT / 16;

    if (MODE == 0 && tid < DM) { sAL[tid] = attn_l[tid]; sAR[tid] = attn_r[tid]; }

    const uint32_t aS = smem_u32(&As[0][0]);
    const uint32_t bS = smem_u32(&Bs[0][0]);
    constexpr uint32_t BUFB = 128 * SPITCH * 4;   // bytes per buffer

    auto load_stage = [&](int buf, int k0) {
        #pragma unroll
        for (int i = 0; i < 2; i++) {
            int chunk = tid + i * 256;          // 0..511 float4 chunks
            int m  = chunk >> 2;                // 0..127
            int kq = (chunk & 3) * 4;           // 0,4,8,12
            uint32_t soff = (uint32_t)(m * SPITCH + kq) * 4 + buf * BUFB;
            int gr = rowBase + m;
            const float* ga = A + (size_t)(gr < NNODES ? gr : 0) * KTOT + k0 + kq;
            cp_async16(aS + soff, ga, (gr < NNODES) ? 16u : 0u);
            const float* gb = Bt + (size_t)(colBase + m) * KTOT + k0 + kq;
            cp_async16(bS + soff, gb, 16u);
        }
    };

    float acc[2][8][4];
    #pragma unroll
    for (int ms = 0; ms < 2; ms++)
        #pragma unroll
        for (int ns = 0; ns < 8; ns++)
            #pragma unroll
            for (int q = 0; q < 4; q++) acc[ms][ns][q] = 0.0f;

    load_stage(0, 0);
    asm volatile("cp.async.commit_group;" ::: "memory");

    const int arow = warpm * 32 + (lane >> 2);
    const int bcol = warpn * 64 + (lane >> 2);
    const int kln  = lane & 3;

    #pragma unroll 2
    for (int kt = 0; kt < KT; ++kt) {
        const int buf = kt & 1;
        if (kt + 1 < KT) {
            load_stage(buf ^ 1, (kt + 1) * 16);
            asm volatile("cp.async.commit_group;" ::: "memory");
            asm volatile("cp.async.wait_group 1;" ::: "memory");
        } else {
            asm volatile("cp.async.wait_group 0;" ::: "memory");
        }
        __syncthreads();

        const float* Ab = As[buf];
        const float* Bb = Bs[buf];
        #pragma unroll
        for (int sub = 0; sub < 2; sub++) {
            const int kb = sub * 8 + kln;
            uint32_t a[2][4], b[8][2];
            #pragma unroll
            for (int ms = 0; ms < 2; ms++) {
                int r = arow + ms * 16;
                a[ms][0] = __float_as_uint(Ab[r * SPITCH + kb]);
                a[ms][1] = __float_as_uint(Ab[(r + 8) * SPITCH + kb]);
                a[ms][2] = __float_as_uint(Ab[r * SPITCH + kb + 4]);
                a[ms][3] = __float_as_uint(Ab[(r + 8) * SPITCH + kb + 4]);
            }
            #pragma unroll
            for (int ns = 0; ns < 8; ns++) {
                int cco = (bcol + ns * 8) * SPITCH;
                b[ns][0] = __float_as_uint(Bb[cco + sub * 8 + kln]);
                b[ns][1] = __float_as_uint(Bb[cco + sub * 8 + kln + 4]);
            }
            #pragma unroll
            for (int ms = 0; ms < 2; ms++)
                #pragma unroll
                for (int ns = 0; ns < 8; ns++)
                    mma_tf32(acc[ms][ns], a[ms], b[ns]);
        }
        __syncthreads();
    }

    // ---------------- epilogue ----------------
    float slp = 0.0f;
    if (MODE == 1) slp = __ldg(slope);

    #pragma unroll
    for (int ms = 0; ms < 2; ms++) {
        #pragma unroll
        for (int half = 0; half < 2; half++) {
            int r = rowBase + warpm * 32 + ms * 16 + half * 8 + (lane >> 2);
            const bool valid = (r < NNODES);
            float psl[4], psr[4];
            if (MODE == 0) {
                #pragma unroll
                for (int q = 0; q < 4; q++) { psl[q] = 0.f; psr[q] = 0.f; }
            }
            #pragma unroll
            for (int ns = 0; ns < 8; ns++) {
                int cl = warpn * 64 + ns * 8 + (lane & 3) * 2;  // local col
                int c = colBase + cl;
                float v0 = acc[ms][ns][half * 2 + 0];
                float v1 = acc[ms][ns][half * 2 + 1];
                if (MODE == 0) {
                    if (valid)
                        *(float2*)&C[(size_t)r * NCOUT + c] = make_float2(v0, v1);
                    int hh = ns >> 1;
                    psl[hh] += v0 * sAL[cl] + v1 * sAL[cl + 1];
                    psr[hh] += v0 * sAR[cl] + v1 * sAR[cl + 1];
                } else if (MODE == 1) {
                    if (valid) {
                        v0 += __ldg(bias + c);
                        v1 += __ldg(bias + c + 1);
                        v0 = (v0 >= 0.0f) ? v0 : slp * v0;
                        v1 = (v1 >= 0.0f) ? v1 : slp * v1;
                        *(float2*)&C[(size_t)r * NCOUT + c] =
                            make_float2(round_tf32(v0), round_tf32(v1));
                    }
                } else {
                    if (valid) {
                        float2 hv = *(const float2*)&addend[(size_t)r * NCOUT + c];
                        v0 += __ldg(bias + c)     + hv.x;
                        v1 += __ldg(bias + c + 1) + hv.y;
                        *(float2*)&C[(size_t)r * NCOUT + c] = make_float2(v0, v1);
                        *(float2*)&g_xr[(size_t)r * DM + c] =
                            make_float2(round_tf32(v0), round_tf32(v1));
                    }
                }
            }
            if (MODE == 0) {
                #pragma unroll
                for (int d = 1; d <= 2; d <<= 1) {
                    #pragma unroll
                    for (int q = 0; q < 4; q++) {
                        psl[q] += __shfl_xor_sync(0xFFFFFFFFu, psl[q], d);
                        psr[q] += __shfl_xor_sync(0xFFFFFFFFu, psr[q], d);
                    }
                }
                if ((lane & 3) == 0 && valid) {
                    #pragma unroll
                    for (int q = 0; q < 4; q++) {
                        int hidx = r * HH + warpn * 4 + q;
                        g_el[hidx] = psl[q];
                        g_er[hidx] = psr[q];
                    }
                }
            }
        }
    }
}

// ---------------- batched transpose + tf32-round (z = layer) ----------------
__global__ void transpose_rnd(const float* __restrict__ in, float* __restrict__ out,
                              int K, int N)
{
    __shared__ float tile[32][33];
    size_t mat = (size_t)blockIdx.z * K * N;
    int k0 = blockIdx.x * 32, n0 = blockIdx.y * 32;
    int tx = threadIdx.x, ty = threadIdx.y;
    #pragma unroll
    for (int i = 0; i < 4; i++)
        tile[ty + i * 8][tx] = in[mat + (size_t)(k0 + ty + i * 8) * N + n0 + tx];
    __syncthreads();
    #pragma unroll
    for (int i = 0; i < 4; i++)
        out[mat + (size_t)(n0 + ty + i * 8) * K + k0 + tx] = round_tf32(tile[tx][ty + i * 8]);
}

// ---------------- round-copy layer-0 input -----------------------------------
__global__ void round_copy(const float* __restrict__ in, float* __restrict__ out, int n4)
{
    int i = blockIdx.x * blockDim.x + threadIdx.x;
    if (i >= n4) return;
    float4 v = ((const float4*)in)[i];
    v.x = round_tf32(v.x); v.y = round_tf32(v.y);
    v.z = round_tf32(v.z); v.w = round_tf32(v.w);
    ((float4*)out)[i] = v;
}

// ---------------- CSR build (once per call) ----------------------------------
__global__ void csr_zero()
{
    int i = blockIdx.x * blockDim.x + threadIdx.x;
    if (i <= NNODES) g_cnt[i] = 0;
}
__global__ void csr_hist(const int* __restrict__ dst)
{
    int e = blockIdx.x * blockDim.x + threadIdx.x;
    if (e < NEDGES) atomicAdd(&g_cnt[dst[e] + 1], 1);
}
// single-block inclusive scan of g_cnt[0..NNODES]; also writes g_wo = rowptr
__global__ void __launch_bounds__(1024) csr_scan()
{
    __shared__ int warpsum[32];
    const int T = 1024, TOT = NNODES + 1;
    const int ITEMS = (TOT + T - 1) / T;            // 49
    int t = threadIdx.x, lane = t & 31, w = t >> 5;
    int base = t * ITEMS;
    int sum = 0;
    for (int i = 0; i < ITEMS; i++) {
        int idx = base + i;
        if (idx < TOT) sum += g_cnt[idx];
    }
    int v = sum;
    #pragma unroll
    for (int o = 1; o < 32; o <<= 1) {
        int u = __shfl_up_sync(0xFFFFFFFFu, v, o);
        if (lane >= o) v += u;
    }
    if (lane == 31) warpsum[w] = v;
    __syncthreads();
    if (w == 0) {
        int wv = warpsum[lane];
        #pragma unroll
        for (int o = 1; o < 32; o <<= 1) {
            int u = __shfl_up_sync(0xFFFFFFFFu, wv, o);
            if (lane >= o) wv += u;
        }
        warpsum[lane] = wv;
    }
    __syncthreads();
    int excl = v - sum + (w > 0 ? warpsum[w - 1] : 0);
    int run = excl;
    for (int i = 0; i < ITEMS; i++) {
        int idx = base + i;
        if (idx < TOT) {
            run += g_cnt[idx];
            g_cnt[idx] = run;
            if (idx < NNODES) g_wo[idx] = run;
        }
    }
}
__global__ void csr_scatter(const int* __restrict__ src, const int* __restrict__ dst)
{
    int e = blockIdx.x * blockDim.x + threadIdx.x;
    if (e >= NEDGES) return;
    int d = dst[e];
    int pos = atomicAdd(&g_wo[d], 1);
    g_adj[pos] = src[e];
}

// ---------------- warp-per-node: softmax-agg + PReLU + 2x LayerNorm ----------
__global__ void __launch_bounds__(256) gat_agg_ln(
    const float* __restrict__ conv_bias, const float* __restrict__ a_conv,
    const float* __restrict__ ln_scale,  const float* __restrict__ ln_bias)
{
    int n = blockIdx.x * 8 + (threadIdx.x >> 5);
    if (n >= NNODES) return;
    int lane = threadIdx.x & 31;
    int h = lane >> 2;

    float myer = (lane < HH) ? g_er[n * HH + lane] : 0.0f;
    int beg = g_cnt[n], end = g_cnt[n + 1];

    float acc[4] = {0.f, 0.f, 0.f, 0.f};
    float den = 0.f;
    for (int i = beg; i < end; i++) {
        int s = g_adj[i];
        float ex = 0.f;
        if (lane < HH) {
            float lg = g_el[s * HH + lane] + myer;
            lg = (lg >= 0.0f) ? lg : 0.2f * lg;
            ex = __expf(lg);
            den += ex;
        }
        float exb = __shfl_sync(0xFFFFFFFFu, ex, h);
        float4 zv = *(const float4*)&g_z[(size_t)s * DM + lane * 4];
        acc[0] = fmaf(exb, zv.x, acc[0]);
        acc[1] = fmaf(exb, zv.y, acc[1]);
        acc[2] = fmaf(exb, zv.z, acc[2]);
        acc[3] = fmaf(exb, zv.w, acc[3]);
    }
    float denb = fmaxf(__shfl_sync(0xFFFFFFFFu, den, h), 1e-9f);

    int c = lane * 4;
    float4 cb = *(const float4*)&conv_bias[c];
    float a = __ldg(a_conv);
    float v[4] = {acc[0] / denb + cb.x, acc[1] / denb + cb.y,
                  acc[2] / denb + cb.z, acc[3] / denb + cb.w};
    #pragma unroll
    for (int q = 0; q < 4; q++) v[q] = (v[q] >= 0.0f) ? v[q] : a * v[q];

    float s = 0.f, s2 = 0.f;
    #pragma unroll
    for (int q = 0; q < 4; q++) { s += v[q]; s2 += v[q] * v[q]; }
    #pragma unroll
    for (int o = 16; o > 0; o >>= 1) {
        s  += __shfl_xor_sync(0xFFFFFFFFu, s, o);
        s2 += __shfl_xor_sync(0xFFFFFFFFu, s2, o);
    }
    float m = s * (1.0f / DM);
    float var = s2 * (1.0f / DM) - m * m;
    float inv = rsqrtf(var + 1e-5f);
    float4 lsc = *(const float4*)&ln_scale[c];
    float4 lbi = *(const float4*)&ln_bias[c];
    float hv[4];
    hv[0] = (v[0] - m) * inv * lsc.x + lbi.x;
    hv[1] = (v[1] - m) * inv * lsc.y + lbi.y;
    hv[2] = (v[2] - m) * inv * lsc.z + lbi.z;
    hv[3] = (v[3] - m) * inv * lsc.w + lbi.w;
    *(float4*)&g_h[(size_t)n * DM + c] = make_float4(hv[0], hv[1], hv[2], hv[3]);

    float t = 0.f, t2 = 0.f;
    #pragma unroll
    for (int q = 0; q < 4; q++) { t += hv[q]; t2 += hv[q] * hv[q]; }
    #pragma unroll
    for (int o = 16; o > 0; o >>= 1) {
        t  += __shfl_xor_sync(0xFFFFFFFFu, t, o);
        t2 += __shfl_xor_sync(0xFFFFFFFFu, t2, o);
    }
    float m2 = t * (1.0f / DM);
    float var2 = t2 * (1.0f / DM) - m2 * m2;
    float inv2 = rsqrtf(var2 + 1e-5f);
    float4 o4;
    o4.x = round_tf32((hv[0] - m2) * inv2 * lsc.x + lbi.x);
    o4.y = round_tf32((hv[1] - m2) * inv2 * lsc.y + lbi.y);
    o4.z = round_tf32((hv[2] - m2) * inv2 * lsc.z + lbi.z);
    o4.w = round_tf32((hv[3] - m2) * inv2 * lsc.w + lbi.w);
    *(float4*)&g_hn[(size_t)n * DM + c] = o4;
}

// ---------------- launcher ---------------------------------------------------
extern "C" void kernel_launch(void* const* d_in, const int* in_sizes, int n_in,
                              void* d_out, int out_size)
{
    const float* in_feats = (const float*)d_in[0];
    const int*   src      = (const int*)  d_in[1];
    const int*   dst      = (const int*)  d_in[2];
    const float* W        = (const float*)d_in[3];
    const float* attn_l   = (const float*)d_in[4];
    const float* attn_r   = (const float*)d_in[5];
    const float* conv_b   = (const float*)d_in[6];
    const float* a_conv   = (const float*)d_in[7];
    const float* ln_scale = (const float*)d_in[8];
    const float* ln_bias  = (const float*)d_in[9];
    const float* W1       = (const float*)d_in[10];
    const float* b1       = (const float*)d_in[11];
    const float* W2       = (const float*)d_in[12];
    const float* b2       = (const float*)d_in[13];
    const float* a_ff     = (const float*)d_in[14];
    float* out = (float*)d_out;

    float *zP, *xrP, *hP, *hnP, *tP, *btP;
    cudaGetSymbolAddress((void**)&zP,  g_z);
    cudaGetSymbolAddress((void**)&xrP, g_xr);
    cudaGetSymbolAddress((void**)&hP,  g_h);
    cudaGetSymbolAddress((void**)&hnP, g_hn);
    cudaGetSymbolAddress((void**)&tP,  g_t);
    cudaGetSymbolAddress((void**)&btP, g_bt);

    const int E_BLOCKS = (NEDGES + 255) / 256;
    const int RC_BLOCKS = (NNODES * DM / 4 + 255) / 256;

    // batched weight transposes (z = layer)
    transpose_rnd<<<dim3(DM / 32, DM / 32, 3), dim3(32, 8)>>>(W, btP + OFF_W(0), DM, DM);
    transpose_rnd<<<dim3(DM / 32, DFFH / 32, 3), dim3(32, 8)>>>(W1, btP + OFF_W1(0), DM, DFFH);
    transpose_rnd<<<dim3(DFFH / 32, DM / 32, 3), dim3(32, 8)>>>(W2, btP + OFF_W2(0), DFFH, DM);
    round_copy<<<RC_BLOCKS, 256>>>(in_feats, xrP, NNODES * DM / 4);

    // CSR build (graph fixed across layers)
    csr_zero<<<(NNODES + 256) / 256, 256>>>();
    csr_hist<<<E_BLOCKS, 256>>>(dst);
    csr_scan<<<1, 1024>>>();
    csr_scatter<<<E_BLOCKS, 256>>>(src, dst);

    for (int l = 0; l < LL; l++) {
        // z = xr @ W  (+ fused el/er)
        gemm_mma<0, 128, 128><<<dim3(1, MTILES), 256>>>(
            xrP, btP + OFF_W(l), zP, nullptr, nullptr, nullptr,
            attn_l + (size_t)l * DM, attn_r + (size_t)l * DM);

        gat_agg_ln<<<(NNODES + 7) / 8, 256>>>(conv_b + (size_t)l * DM, a_conv + l,
                                              ln_scale + (size_t)l * DM,
                                              ln_bias + (size_t)l * DM);

        // t = round(prelu(hn @ W1 + b1))
        gemm_mma<1, 128, 512><<<dim3(DFFH / 128, MTILES), 256>>>(
            hnP, btP + OFF_W1(l), tP, b1 + (size_t)l * DFFH, a_ff + l, nullptr,
            nullptr, nullptr);

        // out[l] = h + t @ W2 + b2; g_xr = round(out[l])
        gemm_mma<2, 512, 128><<<dim3(1, MTILES), 256>>>(
            tP, btP + OFF_W2(l), out + (size_t)l * NNODES * DM,
            b2 + (size_t)l * DM, nullptr, hP,
            nullptr, nullptr);
    }
}

// round 6
// speedup vs baseline: 2.8341x; 1.0173x over previous
#include <cuda_runtime.h>
#include <math.h>
#include <stdint.h>

#define NNODES 50000
#define NEDGES 600000
#define DM 128
#define HH 8
#define DH 16
#define DFFH 512
#define LL 3
#define MTILES ((NNODES + 127) / 128)   // 391

// ---------------- scratch (static device memory; no allocs allowed) --------
__device__ float g_z [(size_t)NNODES * DM];
__device__ float g_xr[(size_t)NNODES * DM];      // tf32-rounded layer input
__device__ float g_el[(size_t)NNODES * HH];
__device__ float g_er[(size_t)NNODES * HH];
__device__ float g_h  [(size_t)NNODES * DM];
__device__ float g_hn [(size_t)NNODES * DM];     // tf32-rounded
__device__ float g_t  [(size_t)NNODES * DFFH];   // tf32-rounded
__device__ float g_bt [(size_t)3 * (DM * DM + DM * DFFH + DFFH * DM)]; // all W^T
__device__ int   g_cnt[NNODES + 1];              // counts -> rowptr
__device__ int   g_wo [NNODES];                  // scatter write offsets
__device__ int   g_adj[NEDGES];                  // src ids grouped by dst

#define OFF_W(l)  ((size_t)(l) * DM * DM)
#define OFF_W1(l) ((size_t)3 * DM * DM + (size_t)(l) * DM * DFFH)
#define OFF_W2(l) ((size_t)3 * DM * DM + (size_t)3 * DM * DFFH + (size_t)(l) * DFFH * DM)

// ---------------- helpers ------------------------------------------------
__device__ __forceinline__ uint32_t smem_u32(const void* p) {
    uint32_t a;
    asm("{ .reg .u64 t; cvta.to.shared.u64 t, %1; cvt.u32.u64 %0, t; }" : "=r"(a) : "l"(p));
    return a;
}
__device__ __forceinline__ float round_tf32(float x) {
    uint32_t r;
    asm("cvt.rna.tf32.f32 %0, %1;" : "=r"(r) : "f"(x));
    return __uint_as_float(r);
}
__device__ __forceinline__ void cp_async16(uint32_t saddr, const void* gaddr, uint32_t sz) {
    asm volatile("cp.async.cg.shared.global [%0], [%1], 16, %2;"
                 :: "r"(saddr), "l"(gaddr), "r"(sz) : "memory");
}
__device__ __forceinline__ void mma_tf32(float* c, const uint32_t* a, const uint32_t* b) {
    asm volatile("mma.sync.aligned.m16n8k8.row.col.f32.tf32.tf32.f32 "
                 "{%0,%1,%2,%3}, {%4,%5,%6,%7}, {%8,%9}, {%0,%1,%2,%3};"
                 : "+f"(c[0]), "+f"(c[1]), "+f"(c[2]), "+f"(c[3])
                 : "r"(a[0]), "r"(a[1]), "r"(a[2]), "r"(a[3]),
                   "r"(b[0]), "r"(b[1]));
}

// ---------------- tf32 mma.sync GEMM ------------------------------------------
// C[M x NCOUT] = A[M x KTOT] @ Bt^T  (Bt stored [NCOUT x KTOT] K-major)
// MODE 0: C = acc -> g_z; fused el/er epilogue
// MODE 1: C = round_tf32(prelu(acc + bias[col]))   (g_t)
// MODE 2: C = acc + bias[col] + addend[row,col]; also g_xr = round(C)
#define SPITCH 20                         // 16 + 4 pad floats per smem row
#define STAGEB (128 * SPITCH * 4)         // 10240 bytes per matrix per stage
#define NSTAGE 3
#define GSMEM  (2 * NSTAGE * STAGEB)      // 61440 bytes dynamic

template <int MODE, int KTOT, int NCOUT>
__global__ void __launch_bounds__(256, 2) gemm_mma(
    const float* __restrict__ A, const float* __restrict__ Bt,
    float* __restrict__ C,
    const float* __restrict__ bias, const float* __restrict__ slope,
    const float* __restrict__ addend,
    const float* __restrict__ attn_l, const float* __restrict__ attn_r)
{
    extern __shared__ float smem_dyn[];
    __shared__ float sAL[DM], sAR[DM];

    const int tid  = threadIdx.x;
    const int lane = tid & 31;
    const int wid  = tid >> 5;
    const int warpm = wid & 3;          // 4 warps along M (32 rows each)
    const int warpn = wid >> 2;         // 2 warps along N (64 cols each)
    const int rowBase = blockIdx.y * 128;
    const int colBase = blockIdx.x * 128;
    constexpr int KT = KTOT / 16;

    if (MODE == 0 && tid < DM) { sAL[tid] = attn_l[tid]; sAR[tid] = attn_r[tid]; }
    if (MODE == 0) __syncthreads();   // sAL/sAR visible before epilogue use

    const uint32_t aS = smem_u32(smem_dyn);
    const uint32_t bS = aS + NSTAGE * STAGEB;

    auto load_stage = [&](int buf, int k0) {
        #pragma unroll
        for (int i = 0; i < 2; i++) {
            int chunk = tid + i * 256;          // 0..511 float4 chunks
            int m  = chunk >> 2;                // 0..127
            int kq = (chunk & 3) * 4;           // 0,4,8,12
            uint32_t soff = (uint32_t)(m * SPITCH + kq) * 4 + buf * STAGEB;
            int gr = rowBase + m;
            const float* ga = A + (size_t)(gr < NNODES ? gr : 0) * KTOT + k0 + kq;
            cp_async16(aS + soff, ga, (gr < NNODES) ? 16u : 0u);
            const float* gb = Bt + (size_t)(colBase + m) * KTOT + k0 + kq;
            cp_async16(bS + soff, gb, 16u);
        }
        asm volatile("cp.async.commit_group;" ::: "memory");
    };

    float acc[2][8][4];
    #pragma unroll
    for (int ms = 0; ms < 2; ms++)
        #pragma unroll
        for (int ns = 0; ns < 8; ns++)
            #pragma unroll
            for (int q = 0; q < 4; q++) acc[ms][ns][q] = 0.0f;

    // prologue: stages 0 and 1 in flight
    load_stage(0, 0);
    load_stage(1, 16);

    const int arow = warpm * 32 + (lane >> 2);
    const int bcol = warpn * 64 + (lane >> 2);
    const int kln  = lane & 3;

    #pragma unroll 3
    for (int kt = 0; kt < KT; ++kt) {
        // ensure stage kt has arrived (one group may remain in flight)
        if (kt + 1 < KT) asm volatile("cp.async.wait_group 1;" ::: "memory");
        else             asm volatile("cp.async.wait_group 0;" ::: "memory");
        __syncthreads();   // data visible to all warps; all warps done with buf (kt+2)%3

        if (kt + 2 < KT) load_stage((kt + 2) % NSTAGE, (kt + 2) * 16);

        const float* Ab = smem_dyn + (size_t)((kt % NSTAGE) * STAGEB) / 4;
        const float* Bb = Ab + (size_t)(NSTAGE * STAGEB) / 4;
        #pragma unroll
        for (int sub = 0; sub < 2; sub++) {
            const int kb = sub * 8 + kln;
            uint32_t a[2][4], b[8][2];
            #pragma unroll
            for (int ms = 0; ms < 2; ms++) {
                int r = arow + ms * 16;
                a[ms][0] = __float_as_uint(Ab[r * SPITCH + kb]);
                a[ms][1] = __float_as_uint(Ab[(r + 8) * SPITCH + kb]);
                a[ms][2] = __float_as_uint(Ab[r * SPITCH + kb + 4]);
                a[ms][3] = __float_as_uint(Ab[(r + 8) * SPITCH + kb + 4]);
            }
            #pragma unroll
            for (int ns = 0; ns < 8; ns++) {
                int cco = (bcol + ns * 8) * SPITCH;
                b[ns][0] = __float_as_uint(Bb[cco + sub * 8 + kln]);
                b[ns][1] = __float_as_uint(Bb[cco + sub * 8 + kln + 4]);
            }
            #pragma unroll
            for (int ms = 0; ms < 2; ms++)
                #pragma unroll
                for (int ns = 0; ns < 8; ns++)
                    mma_tf32(acc[ms][ns], a[ms], b[ns]);
        }
    }

    // ---------------- epilogue ----------------
    float slp = 0.0f;
    if (MODE == 1) slp = __ldg(slope);

    #pragma unroll
    for (int ms = 0; ms < 2; ms++) {
        #pragma unroll
        for (int half = 0; half < 2; half++) {
            int r = rowBase + warpm * 32 + ms * 16 + half * 8 + (lane >> 2);
            const bool valid = (r < NNODES);
            float psl[4], psr[4];
            if (MODE == 0) {
                #pragma unroll
                for (int q = 0; q < 4; q++) { psl[q] = 0.f; psr[q] = 0.f; }
            }
            #pragma unroll
            for (int ns = 0; ns < 8; ns++) {
                int cl = warpn * 64 + ns * 8 + (lane & 3) * 2;  // local col
                int c = colBase + cl;
                float v0 = acc[ms][ns][half * 2 + 0];
                float v1 = acc[ms][ns][half * 2 + 1];
                if (MODE == 0) {
                    if (valid)
                        *(float2*)&C[(size_t)r * NCOUT + c] = make_float2(v0, v1);
                    int hh = ns >> 1;
                    psl[hh] += v0 * sAL[cl] + v1 * sAL[cl + 1];
                    psr[hh] += v0 * sAR[cl] + v1 * sAR[cl + 1];
                } else if (MODE == 1) {
                    if (valid) {
                        v0 += __ldg(bias + c);
                        v1 += __ldg(bias + c + 1);
                        v0 = (v0 >= 0.0f) ? v0 : slp * v0;
                        v1 = (v1 >= 0.0f) ? v1 : slp * v1;
                        *(float2*)&C[(size_t)r * NCOUT + c] =
                            make_float2(round_tf32(v0), round_tf32(v1));
                    }
                } else {
                    if (valid) {
                        float2 hv = *(const float2*)&addend[(size_t)r * NCOUT + c];
                        v0 += __ldg(bias + c)     + hv.x;
                        v1 += __ldg(bias + c + 1) + hv.y;
                        *(float2*)&C[(size_t)r * NCOUT + c] = make_float2(v0, v1);
                        *(float2*)&g_xr[(size_t)r * DM + c] =
                            make_float2(round_tf32(v0), round_tf32(v1));
                    }
                }
            }
            if (MODE == 0) {
                #pragma unroll
                for (int d = 1; d <= 2; d <<= 1) {
                    #pragma unroll
                    for (int q = 0; q < 4; q++) {
                        psl[q] += __shfl_xor_sync(0xFFFFFFFFu, psl[q], d);
                        psr[q] += __shfl_xor_sync(0xFFFFFFFFu, psr[q], d);
                    }
                }
                if ((lane & 3) == 0 && valid) {
                    #pragma unroll
                    for (int q = 0; q < 4; q++) {
                        int hidx = r * HH + warpn * 4 + q;
                        g_el[hidx] = psl[q];
                        g_er[hidx] = psr[q];
                    }
                }
            }
        }
    }
}

// ---------------- batched transpose + tf32-round (z = layer) ----------------
__global__ void transpose_rnd(const float* __restrict__ in, float* __restrict__ out,
                              int K, int N)
{
    __shared__ float tile[32][33];
    size_t mat = (size_t)blockIdx.z * K * N;
    int k0 = blockIdx.x * 32, n0 = blockIdx.y * 32;
    int tx = threadIdx.x, ty = threadIdx.y;
    #pragma unroll
    for (int i = 0; i < 4; i++)
        tile[ty + i * 8][tx] = in[mat + (size_t)(k0 + ty + i * 8) * N + n0 + tx];
    __syncthreads();
    #pragma unroll
    for (int i = 0; i < 4; i++)
        out[mat + (size_t)(n0 + ty + i * 8) * K + k0 + tx] = round_tf32(tile[tx][ty + i * 8]);
}

// ---------------- round-copy layer-0 input -----------------------------------
__global__ void round_copy(const float* __restrict__ in, float* __restrict__ out, int n4)
{
    int i = blockIdx.x * blockDim.x + threadIdx.x;
    if (i >= n4) return;
    float4 v = ((const float4*)in)[i];
    v.x = round_tf32(v.x); v.y = round_tf32(v.y);
    v.z = round_tf32(v.z); v.w = round_tf32(v.w);
    ((float4*)out)[i] = v;
}

// ---------------- CSR build (once per call) ----------------------------------
__global__ void csr_zero()
{
    int i = blockIdx.x * blockDim.x + threadIdx.x;
    if (i <= NNODES) g_cnt[i] = 0;
}
__global__ void csr_hist(const int* __restrict__ dst)
{
    int e = blockIdx.x * blockDim.x + threadIdx.x;
    if (e < NEDGES) atomicAdd(&g_cnt[dst[e] + 1], 1);
}
// single-block inclusive scan of g_cnt[0..NNODES]; also writes g_wo = rowptr
__global__ void __launch_bounds__(1024) csr_scan()
{
    __shared__ int warpsum[32];
    const int T = 1024, TOT = NNODES + 1;
    const int ITEMS = (TOT + T - 1) / T;            // 49
    int t = threadIdx.x, lane = t & 31, w = t >> 5;
    int base = t * ITEMS;
    int sum = 0;
    for (int i = 0; i < ITEMS; i++) {
        int idx = base + i;
        if (idx < TOT) sum += g_cnt[idx];
    }
    int v = sum;
    #pragma unroll
    for (int o = 1; o < 32; o <<= 1) {
        int u = __shfl_up_sync(0xFFFFFFFFu, v, o);
        if (lane >= o) v += u;
    }
    if (lane == 31) warpsum[w] = v;
    __syncthreads();
    if (w == 0) {
        int wv = warpsum[lane];
        #pragma unroll
        for (int o = 1; o < 32; o <<= 1) {
            int u = __shfl_up_sync(0xFFFFFFFFu, wv, o);
            if (lane >= o) wv += u;
        }
        warpsum[lane] = wv;
    }
    __syncthreads();
    int excl = v - sum + (w > 0 ? warpsum[w - 1] : 0);
    int run = excl;
    for (int i = 0; i < ITEMS; i++) {
        int idx = base + i;
        if (idx < TOT) {
            run += g_cnt[idx];
            g_cnt[idx] = run;
            if (idx < NNODES) g_wo[idx] = run;
        }
    }
}
__global__ void csr_scatter(const int* __restrict__ src, const int* __restrict__ dst)
{
    int e = blockIdx.x * blockDim.x + threadIdx.x;
    if (e >= NEDGES) return;
    int d = dst[e];
    int pos = atomicAdd(&g_wo[d], 1);
    g_adj[pos] = src[e];
}

// ---------------- warp-per-node: softmax-agg + PReLU + 2x LayerNorm ----------
__global__ void __launch_bounds__(256) gat_agg_ln(
    const float* __restrict__ conv_bias, const float* __restrict__ a_conv,
    const float* __restrict__ ln_scale,  const float* __restrict__ ln_bias)
{
    int n = blockIdx.x * 8 + (threadIdx.x >> 5);
    if (n >= NNODES) return;
    int lane = threadIdx.x & 31;
    int h = lane >> 2;

    float myer = (lane < HH) ? g_er[n * HH + lane] : 0.0f;
    int beg = g_cnt[n], end = g_cnt[n + 1];

    float acc[4] = {0.f, 0.f, 0.f, 0.f};
    float den = 0.f;
    for (int i = beg; i < end; i++) {
        int s = g_adj[i];
        float ex = 0.f;
        if (lane < HH) {
            float lg = g_el[s * HH + lane] + myer;
            lg = (lg >= 0.0f) ? lg : 0.2f * lg;
            ex = __expf(lg);
            den += ex;
        }
        float exb = __shfl_sync(0xFFFFFFFFu, ex, h);
        float4 zv = *(const float4*)&g_z[(size_t)s * DM + lane * 4];
        acc[0] = fmaf(exb, zv.x, acc[0]);
        acc[1] = fmaf(exb, zv.y, acc[1]);
        acc[2] = fmaf(exb, zv.z, acc[2]);
        acc[3] = fmaf(exb, zv.w, acc[3]);
    }
    float denb = fmaxf(__shfl_sync(0xFFFFFFFFu, den, h), 1e-9f);

    int c = lane * 4;
    float4 cb = *(const float4*)&conv_bias[c];
    float a = __ldg(a_conv);
    float v[4] = {acc[0] / denb + cb.x, acc[1] / denb + cb.y,
                  acc[2] / denb + cb.z, acc[3] / denb + cb.w};
    #pragma unroll
    for (int q = 0; q < 4; q++) v[q] = (v[q] >= 0.0f) ? v[q] : a * v[q];

    float s = 0.f, s2 = 0.f;
    #pragma unroll
    for (int q = 0; q < 4; q++) { s += v[q]; s2 += v[q] * v[q]; }
    #pragma unroll
    for (int o = 16; o > 0; o >>= 1) {
        s  += __shfl_xor_sync(0xFFFFFFFFu, s, o);
        s2 += __shfl_xor_sync(0xFFFFFFFFu, s2, o);
    }
    float m = s * (1.0f / DM);
    float var = s2 * (1.0f / DM) - m * m;
    float inv = rsqrtf(var + 1e-5f);
    float4 lsc = *(const float4*)&ln_scale[c];
    float4 lbi = *(const float4*)&ln_bias[c];
    float hv[4];
    hv[0] = (v[0] - m) * inv * lsc.x + lbi.x;
    hv[1] = (v[1] - m) * inv * lsc.y + lbi.y;
    hv[2] = (v[2] - m) * inv * lsc.z + lbi.z;
    hv[3] = (v[3] - m) * inv * lsc.w + lbi.w;
    *(float4*)&g_h[(size_t)n * DM + c] = make_float4(hv[0], hv[1], hv[2], hv[3]);

    float t = 0.f, t2 = 0.f;
    #pragma unroll
    for (int q = 0; q < 4; q++) { t += hv[q]; t2 += hv[q] * hv[q]; }
    #pragma unroll
    for (int o = 16; o > 0; o >>= 1) {
        t  += __shfl_xor_sync(0xFFFFFFFFu, t, o);
        t2 += __shfl_xor_sync(0xFFFFFFFFu, t2, o);
    }
    float m2 = t * (1.0f / DM);
    float var2 = t2 * (1.0f / DM) - m2 * m2;
    float inv2 = rsqrtf(var2 + 1e-5f);
    float4 o4;
    o4.x = round_tf32((hv[0] - m2) * inv2 * lsc.x + lbi.x);
    o4.y = round_tf32((hv[1] - m2) * inv2 * lsc.y + lbi.y);
    o4.z = round_tf32((hv[2] - m2) * inv2 * lsc.z + lbi.z);
    o4.w = round_tf32((hv[3] - m2) * inv2 * lsc.w + lbi.w);
    *(float4*)&g_hn[(size_t)n * DM + c] = o4;
}

// ---------------- launcher ---------------------------------------------------
extern "C" void kernel_launch(void* const* d_in, const int* in_sizes, int n_in,
                              void* d_out, int out_size)
{
    const float* in_feats = (const float*)d_in[0];
    const int*   src      = (const int*)  d_in[1];
    const int*   dst      = (const int*)  d_in[2];
    const float* W        = (const float*)d_in[3];
    const float* attn_l   = (const float*)d_in[4];
    const float* attn_r   = (const float*)d_in[5];
    const float* conv_b   = (const float*)d_in[6];
    const float* a_conv   = (const float*)d_in[7];
    const float* ln_scale = (const float*)d_in[8];
    const float* ln_bias  = (const float*)d_in[9];
    const float* W1       = (const float*)d_in[10];
    const float* b1       = (const float*)d_in[11];
    const float* W2       = (const float*)d_in[12];
    const float* b2       = (const float*)d_in[13];
    const float* a_ff     = (const float*)d_in[14];
    float* out = (float*)d_out;

    float *zP, *xrP, *hP, *hnP, *tP, *btP;
    cudaGetSymbolAddress((void**)&zP,  g_z);
    cudaGetSymbolAddress((void**)&xrP, g_xr);
    cudaGetSymbolAddress((void**)&hP,  g_h);
    cudaGetSymbolAddress((void**)&hnP, g_hn);
    cudaGetSymbolAddress((void**)&tP,  g_t);
    cudaGetSymbolAddress((void**)&btP, g_bt);

    cudaFuncSetAttribute(gemm_mma<0, 128, 128>, cudaFuncAttributeMaxDynamicSharedMemorySize, GSMEM);
    cudaFuncSetAttribute(gemm_mma<1, 128, 512>, cudaFuncAttributeMaxDynamicSharedMemorySize, GSMEM);
    cudaFuncSetAttribute(gemm_mma<2, 512, 128>, cudaFuncAttributeMaxDynamicSharedMemorySize, GSMEM);

    const int E_BLOCKS = (NEDGES + 255) / 256;
    const int RC_BLOCKS = (NNODES * DM / 4 + 255) / 256;

    // batched weight transposes (z = layer)
    transpose_rnd<<<dim3(DM / 32, DM / 32, 3), dim3(32, 8)>>>(W, btP + OFF_W(0), DM, DM);
    transpose_rnd<<<dim3(DM / 32, DFFH / 32, 3), dim3(32, 8)>>>(W1, btP + OFF_W1(0), DM, DFFH);
    transpose_rnd<<<dim3(DFFH / 32, DM / 32, 3), dim3(32, 8)>>>(W2, btP + OFF_W2(0), DFFH, DM);
    round_copy<<<RC_BLOCKS, 256>>>(in_feats, xrP, NNODES * DM / 4);

    // CSR build (graph fixed across layers)
    csr_zero<<<(NNODES + 256) / 256, 256>>>();
    csr_hist<<<E_BLOCKS, 256>>>(dst);
    csr_scan<<<1, 1024>>>();
    csr_scatter<<<E_BLOCKS, 256>>>(src, dst);

    for (int l = 0; l < LL; l++) {
        // z = xr @ W  (+ fused el/er)
        gemm_mma<0, 128, 128><<<dim3(1, MTILES), 256, GSMEM>>>(
            xrP, btP + OFF_W(l), zP, nullptr, nullptr, nullptr,
            attn_l + (size_t)l * DM, attn_r + (size_t)l * DM);

        gat_agg_ln<<<(NNODES + 7) / 8, 256>>>(conv_b + (size_t)l * DM, a_conv + l,
                                              ln_scale + (size_t)l * DM,
                                              ln_bias + (size_t)l * DM);

        // t = round(prelu(hn @ W1 + b1))
        gemm_mma<1, 128, 512><<<dim3(DFFH / 128, MTILES), 256, GSMEM>>>(
            hnP, btP + OFF_W1(l), tP, b1 + (size_t)l * DFFH, a_ff + l, nullptr,
            nullptr, nullptr);

        // out[l] = h + t @ W2 + b2; g_xr = round(out[l])
        gemm_mma<2, 512, 128><<<dim3(1, MTILES), 256, GSMEM>>>(
            tP, btP + OFF_W2(l), out + (size_t)l * NNODES * DM,
            b2 + (size_t)l * DM, nullptr, hP,
            nullptr, nullptr);
    }
}

// round 7
// speedup vs baseline: 3.0042x; 1.0600x over previous
#include <cuda_runtime.h>
#include <math.h>
#include <stdint.h>

#define NNODES 50000
#define NEDGES 600000
#define DM 128
#define HH 8
#define DH 16
#define DFFH 512
#define LL 3
#define MTILES ((NNODES + 127) / 128)   // 391

// ---------------- scratch (static device memory; no allocs allowed) --------
__device__ float g_z [(size_t)NNODES * DM];
__device__ float g_xr[(size_t)NNODES * DM];      // tf32-rounded layer input
__device__ float g_el[(size_t)NNODES * HH];
__device__ float g_er[(size_t)NNODES * HH];
__device__ float g_h  [(size_t)NNODES * DM];
__device__ float g_hn [(size_t)NNODES * DM];     // tf32-rounded
__device__ float g_t  [(size_t)NNODES * DFFH];   // tf32-rounded
__device__ float g_bt [(size_t)3 * (DM * DM + DM * DFFH + DFFH * DM)]; // all W^T
__device__ int   g_cnt[NNODES + 1];              // counts -> rowptr
__device__ int   g_wo [NNODES];                  // scatter write offsets
__device__ int   g_adj[NEDGES];                  // src ids grouped by dst

#define OFF_W(l)  ((size_t)(l) * DM * DM)
#define OFF_W1(l) ((size_t)3 * DM * DM + (size_t)(l) * DM * DFFH)
#define OFF_W2(l) ((size_t)3 * DM * DM + (size_t)3 * DM * DFFH + (size_t)(l) * DFFH * DM)

// ---------------- helpers ------------------------------------------------
__device__ __forceinline__ uint32_t smem_u32(const void* p) {
    uint32_t a;
    asm("{ .reg .u64 t; cvta.to.shared.u64 t, %1; cvt.u32.u64 %0, t; }" : "=r"(a) : "l"(p));
    return a;
}
__device__ __forceinline__ float round_tf32(float x) {
    uint32_t r;
    asm("cvt.rna.tf32.f32 %0, %1;" : "=r"(r) : "f"(x));
    return __uint_as_float(r);
}
__device__ __forceinline__ void cp_async16(uint32_t saddr, const void* gaddr, uint32_t sz) {
    asm volatile("cp.async.cg.shared.global [%0], [%1], 16, %2;"
                 :: "r"(saddr), "l"(gaddr), "r"(sz) : "memory");
}
__device__ __forceinline__ void mma_tf32(float* c, const uint32_t* a, const uint32_t* b) {
    asm volatile("mma.sync.aligned.m16n8k8.row.col.f32.tf32.tf32.f32 "
                 "{%0,%1,%2,%3}, {%4,%5,%6,%7}, {%8,%9}, {%0,%1,%2,%3};"
                 : "+f"(c[0]), "+f"(c[1]), "+f"(c[2]), "+f"(c[3])
                 : "r"(a[0]), "r"(a[1]), "r"(a[2]), "r"(a[3]),
                   "r"(b[0]), "r"(b[1]));
}
__device__ __forceinline__ void ldsm4(uint32_t addr, uint32_t& r0, uint32_t& r1,
                                      uint32_t& r2, uint32_t& r3) {
    asm volatile("ldmatrix.sync.aligned.m8n8.x4.shared.b16 {%0,%1,%2,%3}, [%4];"
                 : "=r"(r0), "=r"(r1), "=r"(r2), "=r"(r3) : "r"(addr));
}

// ---------------- tf32 mma.sync GEMM ------------------------------------------
// C[M x NCOUT] = A[M x KTOT] @ Bt^T  (Bt stored [NCOUT x KTOT] K-major)
// MODE 0: C = acc -> g_z; fused el/er epilogue
// MODE 1: C = round_tf32(prelu(acc + bias[col]))   (g_t)
// MODE 2: C = acc + bias[col] + addend[row,col]; also g_xr = round(C)
#define SPITCH 20                         // 16 + 4 pad floats per smem row
#define STAGEB (128 * SPITCH * 4)         // 10240 bytes per matrix per stage
#define NSTAGE 3
#define GSMEM  (2 * NSTAGE * STAGEB)      // 61440 bytes dynamic

template <int MODE, int KTOT, int NCOUT>
__global__ void __launch_bounds__(256, 2) gemm_mma(
    const float* __restrict__ A, const float* __restrict__ Bt,
    float* __restrict__ C,
    const float* __restrict__ bias, const float* __restrict__ slope,
    const float* __restrict__ addend,
    const float* __restrict__ attn_l, const float* __restrict__ attn_r)
{
    extern __shared__ float smem_dyn[];
    __shared__ float sAL[DM], sAR[DM];

    const int tid  = threadIdx.x;
    const int lane = tid & 31;
    const int wid  = tid >> 5;
    const int warpm = wid & 3;          // 4 warps along M (32 rows each)
    const int warpn = wid >> 2;         // 2 warps along N (64 cols each)
    const int rowBase = blockIdx.y * 128;
    const int colBase = blockIdx.x * 128;
    constexpr int KT = KTOT / 16;

    if (MODE == 0 && tid < DM) { sAL[tid] = attn_l[tid]; sAR[tid] = attn_r[tid]; }
    if (MODE == 0) __syncthreads();   // sAL/sAR visible before epilogue use

    const uint32_t aS = smem_u32(smem_dyn);
    const uint32_t bS = aS + NSTAGE * STAGEB;

    // ldmatrix per-lane base addresses (tf32 fragment as 8x8 b16 matrices)
    // A: matrix mi = lane>>3: row = warpm*32 [+ms*16] + (mi&1)*8 + (lane&7),
    //    k-word offset = (mi>>1)*4 [+ sub*8]
    const uint32_t aBase = aS +
        (uint32_t)(((warpm * 32) + (((lane >> 3) & 1) * 8) + (lane & 7)) * SPITCH
                   + (lane >> 4) * 4) * 4;
    // B: matrix mi = lane>>3: n-row = warpn*64 [+ns*8] + (mi>>1)*8 + (lane&7),
    //    k-word offset = (mi&1)*4 [+ sub*8]
    const uint32_t bBase = bS +
        (uint32_t)(((warpn * 64) + ((lane >> 4) * 8) + (lane & 7)) * SPITCH
                   + ((lane >> 3) & 1) * 4) * 4;

    auto load_stage = [&](int buf, int k0) {
        #pragma unroll
        for (int i = 0; i < 2; i++) {
            int chunk = tid + i * 256;          // 0..511 float4 chunks
            int m  = chunk >> 2;                // 0..127
            int kq = (chunk & 3) * 4;           // 0,4,8,12
            uint32_t soff = (uint32_t)(m * SPITCH + kq) * 4 + buf * STAGEB;
            int gr = rowBase + m;
            const float* ga = A + (size_t)(gr < NNODES ? gr : 0) * KTOT + k0 + kq;
            cp_async16(aS + soff, ga, (gr < NNODES) ? 16u : 0u);
            const float* gb = Bt + (size_t)(colBase + m) * KTOT + k0 + kq;
            cp_async16(bS + soff, gb, 16u);
        }
        asm volatile("cp.async.commit_group;" ::: "memory");
    };

    float acc[2][8][4];
    #pragma unroll
    for (int ms = 0; ms < 2; ms++)
        #pragma unroll
        for (int ns = 0; ns < 8; ns++)
            #pragma unroll
            for (int q = 0; q < 4; q++) acc[ms][ns][q] = 0.0f;

    // prologue: stages 0 and 1 in flight
    load_stage(0, 0);
    load_stage(1, 16);

    #pragma unroll 3
    for (int kt = 0; kt < KT; ++kt) {
        if (kt + 1 < KT) asm volatile("cp.async.wait_group 1;" ::: "memory");
        else             asm volatile("cp.async.wait_group 0;" ::: "memory");
        __syncthreads();   // data visible; all warps done with buf (kt+2)%3

        if (kt + 2 < KT) load_stage((kt + 2) % NSTAGE, (kt + 2) * 16);

        const uint32_t sOff = (uint32_t)((kt % NSTAGE) * STAGEB);
        #pragma unroll
        for (int sub = 0; sub < 2; sub++) {
            const uint32_t kOff = sOff + sub * 32;   // sub*8 floats
            uint32_t a[2][4], b[8][2];
            ldsm4(aBase + kOff,
                  a[0][0], a[0][1], a[0][2], a[0][3]);
            ldsm4(aBase + kOff + 16 * SPITCH * 4,
                  a[1][0], a[1][1], a[1][2], a[1][3]);
            #pragma unroll
            for (int p = 0; p < 4; p++) {
                ldsm4(bBase + kOff + (uint32_t)(p * 16 * SPITCH * 4),
                      b[2 * p][0], b[2 * p][1], b[2 * p + 1][0], b[2 * p + 1][1]);
            }
            #pragma unroll
            for (int ms = 0; ms < 2; ms++)
                #pragma unroll
                for (int ns = 0; ns < 8; ns++)
                    mma_tf32(acc[ms][ns], a[ms], b[ns]);
        }
    }

    // ---------------- epilogue ----------------
    float slp = 0.0f;
    if (MODE == 1) slp = __ldg(slope);

    #pragma unroll
    for (int ms = 0; ms < 2; ms++) {
        #pragma unroll
        for (int half = 0; half < 2; half++) {
            int r = rowBase + warpm * 32 + ms * 16 + half * 8 + (lane >> 2);
            const bool valid = (r < NNODES);
            float psl[4], psr[4];
            if (MODE == 0) {
                #pragma unroll
                for (int q = 0; q < 4; q++) { psl[q] = 0.f; psr[q] = 0.f; }
            }
            #pragma unroll
            for (int ns = 0; ns < 8; ns++) {
                int cl = warpn * 64 + ns * 8 + (lane & 3) * 2;  // local col
                int c = colBase + cl;
                float v0 = acc[ms][ns][half * 2 + 0];
                float v1 = acc[ms][ns][half * 2 + 1];
                if (MODE == 0) {
                    if (valid)
                        *(float2*)&C[(size_t)r * NCOUT + c] = make_float2(v0, v1);
                    int hh = ns >> 1;
                    psl[hh] += v0 * sAL[cl] + v1 * sAL[cl + 1];
                    psr[hh] += v0 * sAR[cl] + v1 * sAR[cl + 1];
                } else if (MODE == 1) {
                    if (valid) {
                        v0 += __ldg(bias + c);
                        v1 += __ldg(bias + c + 1);
                        v0 = (v0 >= 0.0f) ? v0 : slp * v0;
                        v1 = (v1 >= 0.0f) ? v1 : slp * v1;
                        *(float2*)&C[(size_t)r * NCOUT + c] =
                            make_float2(round_tf32(v0), round_tf32(v1));
                    }
                } else {
                    if (valid) {
                        float2 hv = *(const float2*)&addend[(size_t)r * NCOUT + c];
                        v0 += __ldg(bias + c)     + hv.x;
                        v1 += __ldg(bias + c + 1) + hv.y;
                        *(float2*)&C[(size_t)r * NCOUT + c] = make_float2(v0, v1);
                        *(float2*)&g_xr[(size_t)r * DM + c] =
                            make_float2(round_tf32(v0), round_tf32(v1));
                    }
                }
            }
            if (MODE == 0) {
                #pragma unroll
                for (int d = 1; d <= 2; d <<= 1) {
                    #pragma unroll
                    for (int q = 0; q < 4; q++) {
                        psl[q] += __shfl_xor_sync(0xFFFFFFFFu, psl[q], d);
                        psr[q] += __shfl_xor_sync(0xFFFFFFFFu, psr[q], d);
                    }
                }
                if ((lane & 3) == 0 && valid) {
                    #pragma unroll
                    for (int q = 0; q < 4; q++) {
                        int hidx = r * HH + warpn * 4 + q;
                        g_el[hidx] = psl[q];
                        g_er[hidx] = psr[q];
                    }
                }
            }
        }
    }
}

// ---------------- batched transpose + tf32-round (z = layer) ----------------
__global__ void transpose_rnd(const float* __restrict__ in, float* __restrict__ out,
                              int K, int N)
{
    __shared__ float tile[32][33];
    size_t mat = (size_t)blockIdx.z * K * N;
    int k0 = blockIdx.x * 32, n0 = blockIdx.y * 32;
    int tx = threadIdx.x, ty = threadIdx.y;
    #pragma unroll
    for (int i = 0; i < 4; i++)
        tile[ty + i * 8][tx] = in[mat + (size_t)(k0 + ty + i * 8) * N + n0 + tx];
    __syncthreads();
    #pragma unroll
    for (int i = 0; i < 4; i++)
        out[mat + (size_t)(n0 + ty + i * 8) * K + k0 + tx] = round_tf32(tile[tx][ty + i * 8]);
}

// ---------------- round-copy layer-0 input -----------------------------------
__global__ void round_copy(const float* __restrict__ in, float* __restrict__ out, int n4)
{
    int i = blockIdx.x * blockDim.x + threadIdx.x;
    if (i >= n4) return;
    float4 v = ((const float4*)in)[i];
    v.x = round_tf32(v.x); v.y = round_tf32(v.y);
    v.z = round_tf32(v.z); v.w = round_tf32(v.w);
    ((float4*)out)[i] = v;
}

// ---------------- CSR build (once per call) ----------------------------------
__global__ void csr_zero()
{
    int i = blockIdx.x * blockDim.x + threadIdx.x;
    if (i <= NNODES) g_cnt[i] = 0;
}
__global__ void csr_hist(const int* __restrict__ dst)
{
    int e = blockIdx.x * blockDim.x + threadIdx.x;
    if (e < NEDGES) atomicAdd(&g_cnt[dst[e] + 1], 1);
}
// single-block inclusive scan of g_cnt[0..NNODES]; also writes g_wo = rowptr
__global__ void __launch_bounds__(1024) csr_scan()
{
    __shared__ int warpsum[32];
    const int T = 1024, TOT = NNODES + 1;
    const int ITEMS = (TOT + T - 1) / T;            // 49
    int t = threadIdx.x, lane = t & 31, w = t >> 5;
    int base = t * ITEMS;
    int sum = 0;
    for (int i = 0; i < ITEMS; i++) {
        int idx = base + i;
        if (idx < TOT) sum += g_cnt[idx];
    }
    int v = sum;
    #pragma unroll
    for (int o = 1; o < 32; o <<= 1) {
        int u = __shfl_up_sync(0xFFFFFFFFu, v, o);
        if (lane >= o) v += u;
    }
    if (lane == 31) warpsum[w] = v;
    __syncthreads();
    if (w == 0) {
        int wv = warpsum[lane];
        #pragma unroll
        for (int o = 1; o < 32; o <<= 1) {
            int u = __shfl_up_sync(0xFFFFFFFFu, wv, o);
            if (lane >= o) wv += u;
        }
        warpsum[lane] = wv;
    }
    __syncthreads();
    int excl = v - sum + (w > 0 ? warpsum[w - 1] : 0);
    int run = excl;
    for (int i = 0; i < ITEMS; i++) {
        int idx = base + i;
        if (idx < TOT) {
            run += g_cnt[idx];
            g_cnt[idx] = run;
            if (idx < NNODES) g_wo[idx] = run;
        }
    }
}
__global__ void csr_scatter(const int* __restrict__ src, const int* __restrict__ dst)
{
    int e = blockIdx.x * blockDim.x + threadIdx.x;
    if (e >= NEDGES) return;
    int d = dst[e];
    int pos = atomicAdd(&g_wo[d], 1);
    g_adj[pos] = src[e];
}

// ---------------- warp-per-node: softmax-agg + PReLU + 2x LayerNorm ----------
__global__ void __launch_bounds__(256) gat_agg_ln(
    const float* __restrict__ conv_bias, const float* __restrict__ a_conv,
    const float* __restrict__ ln_scale,  const float* __restrict__ ln_bias)
{
    int n = blockIdx.x * 8 + (threadIdx.x >> 5);
    if (n >= NNODES) return;
    int lane = threadIdx.x & 31;
    int h = lane >> 2;

    float myer = (lane < HH) ? g_er[n * HH + lane] : 0.0f;
    int beg = g_cnt[n], end = g_cnt[n + 1];

    float acc[4] = {0.f, 0.f, 0.f, 0.f};
    float den = 0.f;
    for (int i = beg; i < end; i++) {
        int s = g_adj[i];
        float ex = 0.f;
        if (lane < HH) {
            float lg = g_el[s * HH + lane] + myer;
            lg = (lg >= 0.0f) ? lg : 0.2f * lg;
            ex = __expf(lg);
            den += ex;
        }
        float exb = __shfl_sync(0xFFFFFFFFu, ex, h);
        float4 zv = *(const float4*)&g_z[(size_t)s * DM + lane * 4];
        acc[0] = fmaf(exb, zv.x, acc[0]);
        acc[1] = fmaf(exb, zv.y, acc[1]);
        acc[2] = fmaf(exb, zv.z, acc[2]);
        acc[3] = fmaf(exb, zv.w, acc[3]);
    }
    float denb = fmaxf(__shfl_sync(0xFFFFFFFFu, den, h), 1e-9f);

    int c = lane * 4;
    float4 cb = *(const float4*)&conv_bias[c];
    float a = __ldg(a_conv);
    float v[4] = {acc[0] / denb + cb.x, acc[1] / denb + cb.y,
                  acc[2] / denb + cb.z, acc[3] / denb + cb.w};
    #pragma unroll
    for (int q = 0; q < 4; q++) v[q] = (v[q] >= 0.0f) ? v[q] : a * v[q];

    float s = 0.f, s2 = 0.f;
    #pragma unroll
    for (int q = 0; q < 4; q++) { s += v[q]; s2 += v[q] * v[q]; }
    #pragma unroll
    for (int o = 16; o > 0; o >>= 1) {
        s  += __shfl_xor_sync(0xFFFFFFFFu, s, o);
        s2 += __shfl_xor_sync(0xFFFFFFFFu, s2, o);
    }
    float m = s * (1.0f / DM);
    float var = s2 * (1.0f / DM) - m * m;
    float inv = rsqrtf(var + 1e-5f);
    float4 lsc = *(const float4*)&ln_scale[c];
    float4 lbi = *(const float4*)&ln_bias[c];
    float hv[4];
    hv[0] = (v[0] - m) * inv * lsc.x + lbi.x;
    hv[1] = (v[1] - m) * inv * lsc.y + lbi.y;
    hv[2] = (v[2] - m) * inv * lsc.z + lbi.z;
    hv[3] = (v[3] - m) * inv * lsc.w + lbi.w;
    *(float4*)&g_h[(size_t)n * DM + c] = make_float4(hv[0], hv[1], hv[2], hv[3]);

    float t = 0.f, t2 = 0.f;
    #pragma unroll
    for (int q = 0; q < 4; q++) { t += hv[q]; t2 += hv[q] * hv[q]; }
    #pragma unroll
    for (int o = 16; o > 0; o >>= 1) {
        t  += __shfl_xor_sync(0xFFFFFFFFu, t, o);
        t2 += __shfl_xor_sync(0xFFFFFFFFu, t2, o);
    }
    float m2 = t * (1.0f / DM);
    float var2 = t2 * (1.0f / DM) - m2 * m2;
    float inv2 = rsqrtf(var2 + 1e-5f);
    float4 o4;
    o4.x = round_tf32((hv[0] - m2) * inv2 * lsc.x + lbi.x);
    o4.y = round_tf32((hv[1] - m2) * inv2 * lsc.y + lbi.y);
    o4.z = round_tf32((hv[2] - m2) * inv2 * lsc.z + lbi.z);
    o4.w = round_tf32((hv[3] - m2) * inv2 * lsc.w + lbi.w);
    *(float4*)&g_hn[(size_t)n * DM + c] = o4;
}

// ---------------- launcher ---------------------------------------------------
extern "C" void kernel_launch(void* const* d_in, const int* in_sizes, int n_in,
                              void* d_out, int out_size)
{
    const float* in_feats = (const float*)d_in[0];
    const int*   src      = (const int*)  d_in[1];
    const int*   dst      = (const int*)  d_in[2];
    const float* W        = (const float*)d_in[3];
    const float* attn_l   = (const float*)d_in[4];
    const float* attn_r   = (const float*)d_in[5];
    const float* conv_b   = (const float*)d_in[6];
    const float* a_conv   = (const float*)d_in[7];
    const float* ln_scale = (const float*)d_in[8];
    const float* ln_bias  = (const float*)d_in[9];
    const float* W1       = (const float*)d_in[10];
    const float* b1       = (const float*)d_in[11];
    const float* W2       = (const float*)d_in[12];
    const float* b2       = (const float*)d_in[13];
    const float* a_ff     = (const float*)d_in[14];
    float* out = (float*)d_out;

    float *zP, *xrP, *hP, *hnP, *tP, *btP;
    cudaGetSymbolAddress((void**)&zP,  g_z);
    cudaGetSymbolAddress((void**)&xrP, g_xr);
    cudaGetSymbolAddress((void**)&hP,  g_h);
    cudaGetSymbolAddress((void**)&hnP, g_hn);
    cudaGetSymbolAddress((void**)&tP,  g_t);
    cudaGetSymbolAddress((void**)&btP, g_bt);

    cudaFuncSetAttribute(gemm_mma<0, 128, 128>, cudaFuncAttributeMaxDynamicSharedMemorySize, GSMEM);
    cudaFuncSetAttribute(gemm_mma<1, 128, 512>, cudaFuncAttributeMaxDynamicSharedMemorySize, GSMEM);
    cudaFuncSetAttribute(gemm_mma<2, 512, 128>, cudaFuncAttributeMaxDynamicSharedMemorySize, GSMEM);

    const int E_BLOCKS = (NEDGES + 255) / 256;
    const int RC_BLOCKS = (NNODES * DM / 4 + 255) / 256;

    // batched weight transposes (z = layer)
    transpose_rnd<<<dim3(DM / 32, DM / 32, 3), dim3(32, 8)>>>(W, btP + OFF_W(0), DM, DM);
    transpose_rnd<<<dim3(DM / 32, DFFH / 32, 3), dim3(32, 8)>>>(W1, btP + OFF_W1(0), DM, DFFH);
    transpose_rnd<<<dim3(DFFH / 32, DM / 32, 3), dim3(32, 8)>>>(W2, btP + OFF_W2(0), DFFH, DM);
    round_copy<<<RC_BLOCKS, 256>>>(in_feats, xrP, NNODES * DM / 4);

    // CSR build (graph fixed across layers)
    csr_zero<<<(NNODES + 256) / 256, 256>>>();
    csr_hist<<<E_BLOCKS, 256>>>(dst);
    csr_scan<<<1, 1024>>>();
    csr_scatter<<<E_BLOCKS, 256>>>(src, dst);

    for (int l = 0; l < LL; l++) {
        // z = xr @ W  (+ fused el/er)
        gemm_mma<0, 128, 128><<<dim3(1, MTILES), 256, GSMEM>>>(
            xrP, btP + OFF_W(l), zP, nullptr, nullptr, nullptr,
            attn_l + (size_t)l * DM, attn_r + (size_t)l * DM);

        gat_agg_ln<<<(NNODES + 7) / 8, 256>>>(conv_b + (size_t)l * DM, a_conv + l,
                                              ln_scale + (size_t)l * DM,
                                              ln_bias + (size_t)l * DM);

        // t = round(prelu(hn @ W1 + b1))
        gemm_mma<1, 128, 512><<<dim3(DFFH / 128, MTILES), 256, GSMEM>>>(
            hnP, btP + OFF_W1(l), tP, b1 + (size_t)l * DFFH, a_ff + l, nullptr,
            nullptr, nullptr);

        // out[l] = h + t @ W2 + b2; g_xr = round(out[l])
        gemm_mma<2, 512, 128><<<dim3(1, MTILES), 256, GSMEM>>>(
            tP, btP + OFF_W2(l), out + (size_t)l * NNODES * DM,
            b2 + (size_t)l * DM, nullptr, hP,
            nullptr, nullptr);
    }
}

// round 8
// speedup vs baseline: 3.1985x; 1.0647x over previous
#include <cuda_runtime.h>
#include <math.h>
#include <stdint.h>

#define NNODES 50000
#define NEDGES 600000
#define DM 128
#define HH 8
#define DH 16
#define DFFH 512
#define LL 3
#define MTILES ((NNODES + 127) / 128)   // 391

// ---------------- scratch (static device memory; no allocs allowed) --------
__device__ float g_z [(size_t)NNODES * DM];
__device__ float g_xr[(size_t)NNODES * DM];      // tf32-rounded layer input
__device__ float g_el[(size_t)NNODES * HH];
__device__ float g_er[(size_t)NNODES * HH];
__device__ float g_h  [(size_t)NNODES * DM];
__device__ float g_hn [(size_t)NNODES * DM];     // tf32-rounded
__device__ float g_bt [(size_t)3 * (DM * DM + DM * DFFH + DFFH * DM)]; // all W^T
__device__ int   g_cnt[NNODES + 1];              // counts -> rowptr
__device__ int   g_wo [NNODES];                  // scatter write offsets
__device__ int   g_adj[NEDGES];                  // src ids grouped by dst

#define OFF_W(l)  ((size_t)(l) * DM * DM)
#define OFF_W1(l) ((size_t)3 * DM * DM + (size_t)(l) * DM * DFFH)
#define OFF_W2(l) ((size_t)3 * DM * DM + (size_t)3 * DM * DFFH + (size_t)(l) * DFFH * DM)

// ---------------- helpers ------------------------------------------------
__device__ __forceinline__ uint32_t smem_u32(const void* p) {
    uint32_t a;
    asm("{ .reg .u64 t; cvta.to.shared.u64 t, %1; cvt.u32.u64 %0, t; }" : "=r"(a) : "l"(p));
    return a;
}
__device__ __forceinline__ float round_tf32(float x) {
    uint32_t r;
    asm("cvt.rna.tf32.f32 %0, %1;" : "=r"(r) : "f"(x));
    return __uint_as_float(r);
}
__device__ __forceinline__ void cp_async16(uint32_t saddr, const void* gaddr, uint32_t sz) {
    asm volatile("cp.async.cg.shared.global [%0], [%1], 16, %2;"
                 :: "r"(saddr), "l"(gaddr), "r"(sz) : "memory");
}
__device__ __forceinline__ void mma_tf32(float* c, const uint32_t* a, const uint32_t* b) {
    asm volatile("mma.sync.aligned.m16n8k8.row.col.f32.tf32.tf32.f32 "
                 "{%0,%1,%2,%3}, {%4,%5,%6,%7}, {%8,%9}, {%0,%1,%2,%3};"
                 : "+f"(c[0]), "+f"(c[1]), "+f"(c[2]), "+f"(c[3])
                 : "r"(a[0]), "r"(a[1]), "r"(a[2]), "r"(a[3]),
                   "r"(b[0]), "r"(b[1]));
}
__device__ __forceinline__ void ldsm4(uint32_t addr, uint32_t& r0, uint32_t& r1,
                                      uint32_t& r2, uint32_t& r3) {
    asm volatile("ldmatrix.sync.aligned.m8n8.x4.shared.b16 {%0,%1,%2,%3}, [%4];"
                 : "=r"(r0), "=r"(r1), "=r"(r2), "=r"(r3) : "r"(addr));
}

#define SPITCH 20                         // 16 + 4 pad floats per smem row
#define STAGEB (128 * SPITCH * 4)         // 10240 bytes per matrix per stage
#define NSTAGE 3
#define GSMEM  (2 * NSTAGE * STAGEB)      // 61440 bytes dynamic (gemm_mma)

// ---------------- tf32 mma.sync GEMM (z-projection, MODE0 only) --------------
template <int MODE, int KTOT, int NCOUT>
__global__ void __launch_bounds__(256, 2) gemm_mma(
    const float* __restrict__ A, const float* __restrict__ Bt,
    float* __restrict__ C,
    const float* __restrict__ attn_l, const float* __restrict__ attn_r)
{
    extern __shared__ float smem_dyn[];
    __shared__ float sAL[DM], sAR[DM];

    const int tid  = threadIdx.x;
    const int lane = tid & 31;
    const int wid  = tid >> 5;
    const int warpm = wid & 3;
    const int warpn = wid >> 2;
    const int rowBase = blockIdx.y * 128;
    const int colBase = blockIdx.x * 128;
    constexpr int KT = KTOT / 16;

    if (tid < DM) { sAL[tid] = attn_l[tid]; sAR[tid] = attn_r[tid]; }
    __syncthreads();

    const uint32_t aS = smem_u32(smem_dyn);
    const uint32_t bS = aS + NSTAGE * STAGEB;

    const uint32_t aBase = aS +
        (uint32_t)(((warpm * 32) + (((lane >> 3) & 1) * 8) + (lane & 7)) * SPITCH
                   + (lane >> 4) * 4) * 4;
    const uint32_t bBase = bS +
        (uint32_t)(((warpn * 64) + ((lane >> 4) * 8) + (lane & 7)) * SPITCH
                   + ((lane >> 3) & 1) * 4) * 4;

    auto load_stage = [&](int buf, int k0) {
        #pragma unroll
        for (int i = 0; i < 2; i++) {
            int chunk = tid + i * 256;
            int m  = chunk >> 2;
            int kq = (chunk & 3) * 4;
            uint32_t soff = (uint32_t)(m * SPITCH + kq) * 4 + buf * STAGEB;
            int gr = rowBase + m;
            const float* ga = A + (size_t)(gr < NNODES ? gr : 0) * KTOT + k0 + kq;
            cp_async16(aS + soff, ga, (gr < NNODES) ? 16u : 0u);
            const float* gb = Bt + (size_t)(colBase + m) * KTOT + k0 + kq;
            cp_async16(bS + soff, gb, 16u);
        }
        asm volatile("cp.async.commit_group;" ::: "memory");
    };

    float acc[2][8][4];
    #pragma unroll
    for (int ms = 0; ms < 2; ms++)
        #pragma unroll
        for (int ns = 0; ns < 8; ns++)
            #pragma unroll
            for (int q = 0; q < 4; q++) acc[ms][ns][q] = 0.0f;

    load_stage(0, 0);
    load_stage(1, 16);

    #pragma unroll 3
    for (int kt = 0; kt < KT; ++kt) {
        if (kt + 1 < KT) asm volatile("cp.async.wait_group 1;" ::: "memory");
        else             asm volatile("cp.async.wait_group 0;" ::: "memory");
        __syncthreads();
        if (kt + 2 < KT) load_stage((kt + 2) % NSTAGE, (kt + 2) * 16);

        const uint32_t sOff = (uint32_t)((kt % NSTAGE) * STAGEB);
        #pragma unroll
        for (int sub = 0; sub < 2; sub++) {
            const uint32_t kOff = sOff + sub * 32;
            uint32_t a[2][4], b[8][2];
            ldsm4(aBase + kOff, a[0][0], a[0][1], a[0][2], a[0][3]);
            ldsm4(aBase + kOff + 16 * SPITCH * 4, a[1][0], a[1][1], a[1][2], a[1][3]);
            #pragma unroll
            for (int p = 0; p < 4; p++)
                ldsm4(bBase + kOff + (uint32_t)(p * 16 * SPITCH * 4),
                      b[2 * p][0], b[2 * p][1], b[2 * p + 1][0], b[2 * p + 1][1]);
            #pragma unroll
            for (int ms = 0; ms < 2; ms++)
                #pragma unroll
                for (int ns = 0; ns < 8; ns++)
                    mma_tf32(acc[ms][ns], a[ms], b[ns]);
        }
    }

    // epilogue: store z + fused el/er
    #pragma unroll
    for (int ms = 0; ms < 2; ms++) {
        #pragma unroll
        for (int half = 0; half < 2; half++) {
            int r = rowBase + warpm * 32 + ms * 16 + half * 8 + (lane >> 2);
            const bool valid = (r < NNODES);
            float psl[4], psr[4];
            #pragma unroll
            for (int q = 0; q < 4; q++) { psl[q] = 0.f; psr[q] = 0.f; }
            #pragma unroll
            for (int ns = 0; ns < 8; ns++) {
                int cl = warpn * 64 + ns * 8 + (lane & 3) * 2;
                int c = colBase + cl;
                float v0 = acc[ms][ns][half * 2 + 0];
                float v1 = acc[ms][ns][half * 2 + 1];
                if (valid)
                    *(float2*)&C[(size_t)r * NCOUT + c] = make_float2(v0, v1);
                int hh = ns >> 1;
                psl[hh] += v0 * sAL[cl] + v1 * sAL[cl + 1];
                psr[hh] += v0 * sAR[cl] + v1 * sAR[cl + 1];
            }
            #pragma unroll
            for (int d = 1; d <= 2; d <<= 1) {
                #pragma unroll
                for (int q = 0; q < 4; q++) {
                    psl[q] += __shfl_xor_sync(0xFFFFFFFFu, psl[q], d);
                    psr[q] += __shfl_xor_sync(0xFFFFFFFFu, psr[q], d);
                }
            }
            if ((lane & 3) == 0 && valid) {
                #pragma unroll
                for (int q = 0; q < 4; q++) {
                    int hidx = r * HH + warpn * 4 + q;
                    g_el[hidx] = psl[q];
                    g_er[hidx] = psr[q];
                }
            }
        }
    }
}

// ---------------- fused FeedForward: out = h + prelu(hn@W1+b1)@W2 + b2 -------
// t (tf32-rounded) lives only in shared memory.
#define FP 132                                   // 128 + 4 pad
#define FF_ABYTES (128 * FP * 4)                 // 67584 per A tile
#define FF_SMEM   (2 * FF_ABYTES + NSTAGE * STAGEB)   // 165888

__global__ void __launch_bounds__(256, 1) ff_fused(
    const float* __restrict__ hn, const float* __restrict__ Bt1,
    const float* __restrict__ Bt2,
    const float* __restrict__ b1, const float* __restrict__ slope,
    const float* __restrict__ b2, const float* __restrict__ hres,
    float* __restrict__ Cout, float* __restrict__ xr)
{
    extern __shared__ float smem[];
    const int tid  = threadIdx.x;
    const int lane = tid & 31;
    const int wid  = tid >> 5;
    const int warpm = wid & 3;
    const int warpn = wid >> 2;
    const int rowBase = blockIdx.x * 128;

    const uint32_t hnS = smem_u32(smem);
    const uint32_t tS  = hnS + FF_ABYTES;
    const uint32_t bS  = tS + FF_ABYTES;
    float* tPtr = smem + 128 * FP;   // generic pointer for t writes

    const uint32_t aLane =
        (uint32_t)(((warpm * 32) + (((lane >> 3) & 1) * 8) + (lane & 7)) * FP
                   + (lane >> 4) * 4) * 4;
    const uint32_t bLane =
        (uint32_t)(((warpn * 64) + ((lane >> 4) * 8) + (lane & 7)) * SPITCH
                   + ((lane >> 3) & 1) * 4) * 4;

    // load hn block (128 x 128) into hn_s
    #pragma unroll
    for (int i = 0; i < 16; i++) {
        int chunk = tid + i * 256;
        int m = chunk >> 5;
        int q = (chunk & 31) * 4;
        int gr = rowBase + m;
        cp_async16(hnS + (uint32_t)(m * FP + q) * 4,
                   hn + (size_t)(gr < NNODES ? gr : 0) * DM + q,
                   (gr < NNODES) ? 16u : 0u);
    }
    asm volatile("cp.async.commit_group;" ::: "memory");

    float accO[2][8][4];
    #pragma unroll
    for (int ms = 0; ms < 2; ms++)
        #pragma unroll
        for (int ns = 0; ns < 8; ns++)
            #pragma unroll
            for (int q = 0; q < 4; q++) accO[ms][ns][q] = 0.0f;

    const float slp = __ldg(slope);

    // inner GEMM: acc += A(smem, pitch FP) @ B(global K-major, rowstride bstr)
    auto run_gemm = [&](uint32_t aSm, const float* Bbase, int bstr,
                        float (*acc)[8][4]) {
        auto loadB = [&](int buf, int kt) {
            #pragma unroll
            for (int i = 0; i < 2; i++) {
                int chunk = tid + i * 256;
                int row = chunk >> 2;
                int kq = (chunk & 3) * 4;
                cp_async16(bS + (uint32_t)(row * SPITCH + kq) * 4 + buf * STAGEB,
                           Bbase + (size_t)row * bstr + kt * 16 + kq, 16u);
            }
            asm volatile("cp.async.commit_group;" ::: "memory");
        };
        loadB(0, 0);
        loadB(1, 1);
        #pragma unroll
        for (int kt = 0; kt < 8; kt++) {
            if (kt + 1 < 8) asm volatile("cp.async.wait_group 1;" ::: "memory");
            else            asm volatile("cp.async.wait_group 0;" ::: "memory");
            __syncthreads();
            if (kt + 2 < 8) loadB((kt + 2) % NSTAGE, kt + 2);

            const uint32_t sOff = (uint32_t)((kt % NSTAGE) * STAGEB);
            #pragma unroll
            for (int sub = 0; sub < 2; sub++) {
                uint32_t a[2][4], b[8][2];
                const uint32_t ak = aSm + aLane + (uint32_t)(kt * 16 + sub * 8) * 4;
                ldsm4(ak, a[0][0], a[0][1], a[0][2], a[0][3]);
                ldsm4(ak + 16 * FP * 4, a[1][0], a[1][1], a[1][2], a[1][3]);
                const uint32_t bk = bS + bLane + sOff + sub * 32;
                #pragma unroll
                for (int p = 0; p < 4; p++)
                    ldsm4(bk + (uint32_t)(p * 16 * SPITCH * 4),
                          b[2 * p][0], b[2 * p][1], b[2 * p + 1][0], b[2 * p + 1][1]);
                #pragma unroll
                for (int ms = 0; ms < 2; ms++)
                    #pragma unroll
                    for (int ns = 0; ns < 8; ns++)
                        mma_tf32(acc[ms][ns], a[ms], b[ns]);
            }
        }
    };

    #pragma unroll 1
    for (int c = 0; c < 4; c++) {
        // ---- stage 1: t_chunk = round(prelu(hn_s @ W1_chunk + b1_chunk)) ----
        float accT[2][8][4];
        #pragma unroll
        for (int ms = 0; ms < 2; ms++)
            #pragma unroll
            for (int ns = 0; ns < 8; ns++)
                #pragma unroll
                for (int q = 0; q < 4; q++) accT[ms][ns][q] = 0.0f;

        run_gemm(hnS, Bt1 + (size_t)(c * 128) * DM, DM, accT);

        __syncthreads();   // all warps done reading t_s (previous chunk stage 2)
        const float* b1c = b1 + c * 128;
        #pragma unroll
        for (int ms = 0; ms < 2; ms++) {
            #pragma unroll
            for (int half = 0; half < 2; half++) {
                int r = warpm * 32 + ms * 16 + half * 8 + (lane >> 2);
                #pragma unroll
                for (int ns = 0; ns < 8; ns++) {
                    int cl = warpn * 64 + ns * 8 + (lane & 3) * 2;
                    float v0 = accT[ms][ns][half * 2 + 0] + __ldg(b1c + cl);
                    float v1 = accT[ms][ns][half * 2 + 1] + __ldg(b1c + cl + 1);
                    v0 = (v0 >= 0.0f) ? v0 : slp * v0;
                    v1 = (v1 >= 0.0f) ? v1 : slp * v1;
                    *(float2*)&tPtr[r * FP + cl] =
                        make_float2(round_tf32(v0), round_tf32(v1));
                }
            }
        }
        __syncthreads();   // t_s visible

        // ---- stage 2: accO += t_s @ W2_chunk ----
        run_gemm(tS, Bt2 + (size_t)(c * 128), DFFH, accO);
    }

    // ---- final epilogue: out = accO + b2 + h; xr = round(out) ----
    #pragma unroll
    for (int ms = 0; ms < 2; ms++) {
        #pragma unroll
        for (int half = 0; half < 2; half++) {
            int r = rowBase + warpm * 32 + ms * 16 + half * 8 + (lane >> 2);
            if (r >= NNODES) continue;
            #pragma unroll
            for (int ns = 0; ns < 8; ns++) {
                int cl = warpn * 64 + ns * 8 + (lane & 3) * 2;
                float2 hv = *(const float2*)&hres[(size_t)r * DM + cl];
                float v0 = accO[ms][ns][half * 2 + 0] + __ldg(b2 + cl)     + hv.x;
                float v1 = accO[ms][ns][half * 2 + 1] + __ldg(b2 + cl + 1) + hv.y;
                *(float2*)&Cout[(size_t)r * DM + cl] = make_float2(v0, v1);
                *(float2*)&xr[(size_t)r * DM + cl] =
                    make_float2(round_tf32(v0), round_tf32(v1));
            }
        }
    }
}

// ---------------- batched transpose + tf32-round (z = layer) ----------------
__global__ void transpose_rnd(const float* __restrict__ in, float* __restrict__ out,
                              int K, int N)
{
    __shared__ float tile[32][33];
    size_t mat = (size_t)blockIdx.z * K * N;
    int k0 = blockIdx.x * 32, n0 = blockIdx.y * 32;
    int tx = threadIdx.x, ty = threadIdx.y;
    #pragma unroll
    for (int i = 0; i < 4; i++)
        tile[ty + i * 8][tx] = in[mat + (size_t)(k0 + ty + i * 8) * N + n0 + tx];
    __syncthreads();
    #pragma unroll
    for (int i = 0; i < 4; i++)
        out[mat + (size_t)(n0 + ty + i * 8) * K + k0 + tx] = round_tf32(tile[tx][ty + i * 8]);
}

// ---------------- round-copy layer-0 input -----------------------------------
__global__ void round_copy(const float* __restrict__ in, float* __restrict__ out, int n4)
{
    int i = blockIdx.x * blockDim.x + threadIdx.x;
    if (i >= n4) return;
    float4 v = ((const float4*)in)[i];
    v.x = round_tf32(v.x); v.y = round_tf32(v.y);
    v.z = round_tf32(v.z); v.w = round_tf32(v.w);
    ((float4*)out)[i] = v;
}

// ---------------- CSR build (once per call) ----------------------------------
__global__ void csr_zero()
{
    int i = blockIdx.x * blockDim.x + threadIdx.x;
    if (i <= NNODES) g_cnt[i] = 0;
}
__global__ void csr_hist(const int* __restrict__ dst)
{
    int e = blockIdx.x * blockDim.x + threadIdx.x;
    if (e < NEDGES) atomicAdd(&g_cnt[dst[e] + 1], 1);
}
__global__ void __launch_bounds__(1024) csr_scan()
{
    __shared__ int warpsum[32];
    const int T = 1024, TOT = NNODES + 1;
    const int ITEMS = (TOT + T - 1) / T;
    int t = threadIdx.x, lane = t & 31, w = t >> 5;
    int base = t * ITEMS;
    int sum = 0;
    for (int i = 0; i < ITEMS; i++) {
        int idx = base + i;
        if (idx < TOT) sum += g_cnt[idx];
    }
    int v = sum;
    #pragma unroll
    for (int o = 1; o < 32; o <<= 1) {
        int u = __shfl_up_sync(0xFFFFFFFFu, v, o);
        if (lane >= o) v += u;
    }
    if (lane == 31) warpsum[w] = v;
    __syncthreads();
    if (w == 0) {
        int wv = warpsum[lane];
        #pragma unroll
        for (int o = 1; o < 32; o <<= 1) {
            int u = __shfl_up_sync(0xFFFFFFFFu, wv, o);
            if (lane >= o) wv += u;
        }
        warpsum[lane] = wv;
    }
    __syncthreads();
    int excl = v - sum + (w > 0 ? warpsum[w - 1] : 0);
    int run = excl;
    for (int i = 0; i < ITEMS; i++) {
        int idx = base + i;
        if (idx < TOT) {
            run += g_cnt[idx];
            g_cnt[idx] = run;
            if (idx < NNODES) g_wo[idx] = run;
        }
    }
}
__global__ void csr_scatter(const int* __restrict__ src, const int* __restrict__ dst)
{
    int e = blockIdx.x * blockDim.x + threadIdx.x;
    if (e >= NEDGES) return;
    int d = dst[e];
    int pos = atomicAdd(&g_wo[d], 1);
    g_adj[pos] = src[e];
}

// ---------------- warp-per-node: softmax-agg + PReLU + 2x LayerNorm ----------
__global__ void __launch_bounds__(256) gat_agg_ln(
    const float* __restrict__ conv_bias, const float* __restrict__ a_conv,
    const float* __restrict__ ln_scale,  const float* __restrict__ ln_bias)
{
    int n = blockIdx.x * 8 + (threadIdx.x >> 5);
    if (n >= NNODES) return;
    int lane = threadIdx.x & 31;
    int h = lane >> 2;

    float myer = (lane < HH) ? g_er[n * HH + lane] : 0.0f;
    int beg = g_cnt[n], end = g_cnt[n + 1];

    float acc[4] = {0.f, 0.f, 0.f, 0.f};
    float den = 0.f;
    int i = beg;
    #pragma unroll 1
    for (; i + 2 <= end; i += 2) {
        int s0 = g_adj[i], s1 = g_adj[i + 1];
        float ex0 = 0.f, ex1 = 0.f;
        if (lane < HH) {
            float l0 = g_el[s0 * HH + lane] + myer;
            float l1 = g_el[s1 * HH + lane] + myer;
            l0 = (l0 >= 0.0f) ? l0 : 0.2f * l0;
            l1 = (l1 >= 0.0f) ? l1 : 0.2f * l1;
            ex0 = __expf(l0);
            ex1 = __expf(l1);
            den += ex0 + ex1;
        }
        float eb0 = __shfl_sync(0xFFFFFFFFu, ex0, h);
        float eb1 = __shfl_sync(0xFFFFFFFFu, ex1, h);
        float4 z0 = *(const float4*)&g_z[(size_t)s0 * DM + lane * 4];
        float4 z1 = *(const float4*)&g_z[(size_t)s1 * DM + lane * 4];
        acc[0] = fmaf(eb0, z0.x, acc[0]);
        acc[1] = fmaf(eb0, z0.y, acc[1]);
        acc[2] = fmaf(eb0, z0.z, acc[2]);
        acc[3] = fmaf(eb0, z0.w, acc[3]);
        acc[0] = fmaf(eb1, z1.x, acc[0]);
        acc[1] = fmaf(eb1, z1.y, acc[1]);
        acc[2] = fmaf(eb1, z1.z, acc[2]);
        acc[3] = fmaf(eb1, z1.w, acc[3]);
    }
    if (i < end) {
        int s = g_adj[i];
        float ex = 0.f;
        if (lane < HH) {
            float lg = g_el[s * HH + lane] + myer;
            lg = (lg >= 0.0f) ? lg : 0.2f * lg;
            ex = __expf(lg);
            den += ex;
        }
        float exb = __shfl_sync(0xFFFFFFFFu, ex, h);
        float4 zv = *(const float4*)&g_z[(size_t)s * DM + lane * 4];
        acc[0] = fmaf(exb, zv.x, acc[0]);
        acc[1] = fmaf(exb, zv.y, acc[1]);
        acc[2] = fmaf(exb, zv.z, acc[2]);
        acc[3] = fmaf(exb, zv.w, acc[3]);
    }
    float denb = fmaxf(__shfl_sync(0xFFFFFFFFu, den, h), 1e-9f);

    int c = lane * 4;
    float4 cb = *(const float4*)&conv_bias[c];
    float a = __ldg(a_conv);
    float v[4] = {acc[0] / denb + cb.x, acc[1] / denb + cb.y,
                  acc[2] / denb + cb.z, acc[3] / denb + cb.w};
    #pragma unroll
    for (int q = 0; q < 4; q++) v[q] = (v[q] >= 0.0f) ? v[q] : a * v[q];

    float s = 0.f, s2 = 0.f;
    #pragma unroll
    for (int q = 0; q < 4; q++) { s += v[q]; s2 += v[q] * v[q]; }
    #pragma unroll
    for (int o = 16; o > 0; o >>= 1) {
        s  += __shfl_xor_sync(0xFFFFFFFFu, s, o);
        s2 += __shfl_xor_sync(0xFFFFFFFFu, s2, o);
    }
    float m = s * (1.0f / DM);
    float var = s2 * (1.0f / DM) - m * m;
    float inv = rsqrtf(var + 1e-5f);
    float4 lsc = *(const float4*)&ln_scale[c];
    float4 lbi = *(const float4*)&ln_bias[c];
    float hv[4];
    hv[0] = (v[0] - m) * inv * lsc.x + lbi.x;
    hv[1] = (v[1] - m) * inv * lsc.y + lbi.y;
    hv[2] = (v[2] - m) * inv * lsc.z + lbi.z;
    hv[3] = (v[3] - m) * inv * lsc.w + lbi.w;
    *(float4*)&g_h[(size_t)n * DM + c] = make_float4(hv[0], hv[1], hv[2], hv[3]);

    float t = 0.f, t2 = 0.f;
    #pragma unroll
    for (int q = 0; q < 4; q++) { t += hv[q]; t2 += hv[q] * hv[q]; }
    #pragma unroll
    for (int o = 16; o > 0; o >>= 1) {
        t  += __shfl_xor_sync(0xFFFFFFFFu, t, o);
        t2 += __shfl_xor_sync(0xFFFFFFFFu, t2, o);
    }
    float m2 = t * (1.0f / DM);
    float var2 = t2 * (1.0f / DM) - m2 * m2;
    float inv2 = rsqrtf(var2 + 1e-5f);
    float4 o4;
    o4.x = round_tf32((hv[0] - m2) * inv2 * lsc.x + lbi.x);
    o4.y = round_tf32((hv[1] - m2) * inv2 * lsc.y + lbi.y);
    o4.z = round_tf32((hv[2] - m2) * inv2 * lsc.z + lbi.z);
    o4.w = round_tf32((hv[3] - m2) * inv2 * lsc.w + lbi.w);
    *(float4*)&g_hn[(size_t)n * DM + c] = o4;
}

// ---------------- launcher ---------------------------------------------------
extern "C" void kernel_launch(void* const* d_in, const int* in_sizes, int n_in,
                              void* d_out, int out_size)
{
    const float* in_feats = (const float*)d_in[0];
    const int*   src      = (const int*)  d_in[1];
    const int*   dst      = (const int*)  d_in[2];
    const float* W        = (const float*)d_in[3];
    const float* attn_l   = (const float*)d_in[4];
    const float* attn_r   = (const float*)d_in[5];
    const float* conv_b   = (const float*)d_in[6];
    const float* a_conv   = (const float*)d_in[7];
    const float* ln_scale = (const float*)d_in[8];
    const float* ln_bias  = (const float*)d_in[9];
    const float* W1       = (const float*)d_in[10];
    const float* b1       = (const float*)d_in[11];
    const float* W2       = (const float*)d_in[12];
    const float* b2       = (const float*)d_in[13];
    const float* a_ff     = (const float*)d_in[14];
    float* out = (float*)d_out;

    float *zP, *xrP, *hP, *hnP, *btP;
    cudaGetSymbolAddress((void**)&zP,  g_z);
    cudaGetSymbolAddress((void**)&xrP, g_xr);
    cudaGetSymbolAddress((void**)&hP,  g_h);
    cudaGetSymbolAddress((void**)&hnP, g_hn);
    cudaGetSymbolAddress((void**)&btP, g_bt);

    cudaFuncSetAttribute(gemm_mma<0, 128, 128>, cudaFuncAttributeMaxDynamicSharedMemorySize, GSMEM);
    cudaFuncSetAttribute(ff_fused, cudaFuncAttributeMaxDynamicSharedMemorySize, FF_SMEM);

    const int E_BLOCKS = (NEDGES + 255) / 256;
    const int RC_BLOCKS = (NNODES * DM / 4 + 255) / 256;

    // batched weight transposes (z = layer)
    transpose_rnd<<<dim3(DM / 32, DM / 32, 3), dim3(32, 8)>>>(W, btP + OFF_W(0), DM, DM);
    transpose_rnd<<<dim3(DM / 32, DFFH / 32, 3), dim3(32, 8)>>>(W1, btP + OFF_W1(0), DM, DFFH);
    transpose_rnd<<<dim3(DFFH / 32, DM / 32, 3), dim3(32, 8)>>>(W2, btP + OFF_W2(0), DFFH, DM);
    round_copy<<<RC_BLOCKS, 256>>>(in_feats, xrP, NNODES * DM / 4);

    // CSR build (graph fixed across layers)
    csr_zero<<<(NNODES + 256) / 256, 256>>>();
    csr_hist<<<E_BLOCKS, 256>>>(dst);
    csr_scan<<<1, 1024>>>();
    csr_scatter<<<E_BLOCKS, 256>>>(src, dst);

    for (int l = 0; l < LL; l++) {
        // z = xr @ W  (+ fused el/er)
        gemm_mma<0, 128, 128><<<dim3(1, MTILES), 256, GSMEM>>>(
            xrP, btP + OFF_W(l), zP,
            attn_l + (size_t)l * DM, attn_r + (size_t)l * DM);

        gat_agg_ln<<<(NNODES + 7) / 8, 256>>>(conv_b + (size_t)l * DM, a_conv + l,
                                              ln_scale + (size_t)l * DM,
                                              ln_bias + (size_t)l * DM);

        // out[l] = h + prelu(hn@W1+b1)@W2 + b2 ; xr = round(out[l])
        ff_fused<<<MTILES, 256, FF_SMEM>>>(
            hnP, btP + OFF_W1(l), btP + OFF_W2(l),
            b1 + (size_t)l * DFFH, a_ff + l, b2 + (size_t)l * DM,
            hP, out + (size_t)l * NNODES * DM, xrP);
    }
}

// round 9
// speedup vs baseline: 3.9180x; 1.2250x over previous
#include <cuda_runtime.h>
#include <cuda_fp16.h>
#include <math.h>
#include <stdint.h>

#define NNODES 50000
#define NEDGES 600000
#define DM 128
#define HH 8
#define DH 16
#define DFFH 512
#define LL 3
#define MTILES ((NNODES + 127) / 128)   // 391
#define FTILES ((NNODES + 63) / 64)     // 782

// ---------------- scratch (static device memory; no allocs allowed) --------
__device__ float  g_z [(size_t)NNODES * DM];
__device__ __half g_xr[(size_t)NNODES * DM];     // fp16 layer input
__device__ float  g_el[(size_t)NNODES * HH];
__device__ float  g_er[(size_t)NNODES * HH];
__device__ float  g_h [(size_t)NNODES * DM];
__device__ __half g_hn[(size_t)NNODES * DM];     // fp16
__device__ __half g_bt[(size_t)3 * (DM * DM + DM * DFFH + DFFH * DM)]; // all W^T fp16
__device__ int    g_cnt[NNODES + 1];             // counts -> rowptr
__device__ int    g_wo [NNODES];                 // scatter write offsets
__device__ int    g_adj[NEDGES];                 // src ids grouped by dst

#define OFF_W(l)  ((size_t)(l) * DM * DM)
#define OFF_W1(l) ((size_t)3 * DM * DM + (size_t)(l) * DM * DFFH)
#define OFF_W2(l) ((size_t)3 * DM * DM + (size_t)3 * DM * DFFH + (size_t)(l) * DFFH * DM)

// ---------------- helpers ------------------------------------------------
__device__ __forceinline__ uint32_t smem_u32(const void* p) {
    uint32_t a;
    asm("{ .reg .u64 t; cvta.to.shared.u64 t, %1; cvt.u32.u64 %0, t; }" : "=r"(a) : "l"(p));
    return a;
}
__device__ __forceinline__ void cp_async16(uint32_t saddr, const void* gaddr, uint32_t sz) {
    asm volatile("cp.async.cg.shared.global [%0], [%1], 16, %2;"
                 :: "r"(saddr), "l"(gaddr), "r"(sz) : "memory");
}
// fp16 mma: D(f32) += A(f16, m16k16) * B(f16, k16n8)
__device__ __forceinline__ void mma_f16(float* c, const uint32_t* a, const uint32_t* b) {
    asm volatile("mma.sync.aligned.m16n8k16.row.col.f32.f16.f16.f32 "
                 "{%0,%1,%2,%3}, {%4,%5,%6,%7}, {%8,%9}, {%0,%1,%2,%3};"
                 : "+f"(c[0]), "+f"(c[1]), "+f"(c[2]), "+f"(c[3])
                 : "r"(a[0]), "r"(a[1]), "r"(a[2]), "r"(a[3]),
                   "r"(b[0]), "r"(b[1]));
}
__device__ __forceinline__ void ldsm4(uint32_t addr, uint32_t& r0, uint32_t& r1,
                                      uint32_t& r2, uint32_t& r3) {
    asm volatile("ldmatrix.sync.aligned.m8n8.x4.shared.b16 {%0,%1,%2,%3}, [%4];"
                 : "=r"(r0), "=r"(r1), "=r"(r2), "=r"(r3) : "r"(addr));
}

#define HP 24                              // halves per staged row (16 + 8 pad)
#define HSTAGEB (128 * HP * 2)             // 6144 bytes per matrix per k16 stage
#define NSTAGE 3
#define G0SMEM (2 * NSTAGE * HSTAGEB)      // 36864 bytes

// ---------------- fp16 mma GEMM: z-projection + fused el/er ------------------
// C[M x 128] = A[M x 128] @ Bt^T  (half inputs, fp32 out)
__global__ void __launch_bounds__(256, 2) gemm_z(
    const __half* __restrict__ A, const __half* __restrict__ Bt,
    float* __restrict__ C,
    const float* __restrict__ attn_l, const float* __restrict__ attn_r)
{
    extern __shared__ char smem_raw[];
    __shared__ float sAL[DM], sAR[DM];

    const int tid  = threadIdx.x;
    const int lane = tid & 31;
    const int wid  = tid >> 5;
    const int warpm = wid & 3;          // 4 warps along M (32 rows)
    const int warpn = wid >> 2;         // 2 warps along N (64 cols)
    const int rowBase = blockIdx.y * 128;

    if (tid < DM) { sAL[tid] = attn_l[tid]; sAR[tid] = attn_r[tid]; }
    __syncthreads();

    const uint32_t aS = smem_u32(smem_raw);
    const uint32_t bS = aS + NSTAGE * HSTAGEB;

    // ldmatrix lane addresses (fp16, m16n8k16 fragments)
    const uint32_t aBase = aS +
        (uint32_t)(((warpm * 32) + (((lane >> 3) & 1) * 8) + (lane & 7)) * HP
                   + (lane >> 4) * 8) * 2;
    const uint32_t bBase = bS +
        (uint32_t)(((warpn * 64) + (((lane >> 4) & 1) * 8) + (lane & 7)) * HP
                   + ((lane >> 3) & 1) * 8) * 2;

    auto load_stage = [&](int buf, int k0) {
        int row = tid >> 1;                 // 0..127
        int kc  = (tid & 1) * 8;            // halves
        int gr = rowBase + row;
        cp_async16(aS + (uint32_t)(row * HP + kc) * 2 + buf * HSTAGEB,
                   A + (size_t)(gr < NNODES ? gr : 0) * DM + k0 + kc,
                   (gr < NNODES) ? 16u : 0u);
        cp_async16(bS + (uint32_t)(row * HP + kc) * 2 + buf * HSTAGEB,
                   Bt + (size_t)row * DM + k0 + kc, 16u);
        asm volatile("cp.async.commit_group;" ::: "memory");
    };

    float acc[2][8][4];
    #pragma unroll
    for (int ms = 0; ms < 2; ms++)
        #pragma unroll
        for (int ns = 0; ns < 8; ns++)
            #pragma unroll
            for (int q = 0; q < 4; q++) acc[ms][ns][q] = 0.0f;

    load_stage(0, 0);
    load_stage(1, 16);

    #pragma unroll
    for (int kt = 0; kt < 8; ++kt) {
        if (kt + 1 < 8) asm volatile("cp.async.wait_group 1;" ::: "memory");
        else            asm volatile("cp.async.wait_group 0;" ::: "memory");
        __syncthreads();
        if (kt + 2 < 8) load_stage((kt + 2) % NSTAGE, (kt + 2) * 16);

        const uint32_t kOff = (uint32_t)((kt % NSTAGE) * HSTAGEB);
        uint32_t a[2][4], b[8][2];
        ldsm4(aBase + kOff, a[0][0], a[0][1], a[0][2], a[0][3]);
        ldsm4(aBase + kOff + 16 * HP * 2, a[1][0], a[1][1], a[1][2], a[1][3]);
        #pragma unroll
        for (int p = 0; p < 4; p++)
            ldsm4(bBase + kOff + (uint32_t)(p * 16 * HP * 2),
                  b[2 * p][0], b[2 * p][1], b[2 * p + 1][0], b[2 * p + 1][1]);
        #pragma unroll
        for (int ms = 0; ms < 2; ms++)
            #pragma unroll
            for (int ns = 0; ns < 8; ns++)
                mma_f16(acc[ms][ns], a[ms], b[ns]);
    }

    // epilogue: store z (fp32) + fused el/er
    #pragma unroll
    for (int ms = 0; ms < 2; ms++) {
        #pragma unroll
        for (int half = 0; half < 2; half++) {
            int r = rowBase + warpm * 32 + ms * 16 + half * 8 + (lane >> 2);
            const bool valid = (r < NNODES);
            float psl[4], psr[4];
            #pragma unroll
            for (int q = 0; q < 4; q++) { psl[q] = 0.f; psr[q] = 0.f; }
            #pragma unroll
            for (int ns = 0; ns < 8; ns++) {
                int cl = warpn * 64 + ns * 8 + (lane & 3) * 2;
                float v0 = acc[ms][ns][half * 2 + 0];
                float v1 = acc[ms][ns][half * 2 + 1];
                if (valid)
                    *(float2*)&C[(size_t)r * DM + cl] = make_float2(v0, v1);
                int hh = ns >> 1;
                psl[hh] += v0 * sAL[cl] + v1 * sAL[cl + 1];
                psr[hh] += v0 * sAR[cl] + v1 * sAR[cl + 1];
            }
            #pragma unroll
            for (int d = 1; d <= 2; d <<= 1) {
                #pragma unroll
                for (int q = 0; q < 4; q++) {
                    psl[q] += __shfl_xor_sync(0xFFFFFFFFu, psl[q], d);
                    psr[q] += __shfl_xor_sync(0xFFFFFFFFu, psr[q], d);
                }
            }
            if ((lane & 3) == 0 && valid) {
                #pragma unroll
                for (int q = 0; q < 4; q++) {
                    int hidx = r * HH + warpn * 4 + q;
                    g_el[hidx] = psl[q];
                    g_er[hidx] = psr[q];
                }
            }
        }
    }
}

// ---------------- fused FeedForward (fp16): 64-row blocks --------------------
// out = h + prelu(hn@W1+b1)@W2 + b2 ; xr = fp16(out). t lives in smem (fp16).
#define FPH 136                              // halves pitch for 128-wide tiles
#define FF_A (64 * FPH * 2)                  // 17408 bytes per A tile
#define FF_SMEM (2 * FF_A + NSTAGE * HSTAGEB)    // 53248

__global__ void __launch_bounds__(256, 2) ff_fused(
    const __half* __restrict__ hn, const __half* __restrict__ Bt1,
    const __half* __restrict__ Bt2,
    const float* __restrict__ b1, const float* __restrict__ slope,
    const float* __restrict__ b2, const float* __restrict__ hres,
    float* __restrict__ Cout, __half* __restrict__ xr)
{
    extern __shared__ char smem_raw[];
    const int tid  = threadIdx.x;
    const int lane = tid & 31;
    const int wid  = tid >> 5;
    const int warpm = wid & 1;          // 2 warps along M (32 rows)
    const int warpn = wid >> 1;         // 4 warps along N (32 cols)
    const int rowBase = blockIdx.x * 64;

    const uint32_t hnS = smem_u32(smem_raw);
    const uint32_t tS  = hnS + FF_A;
    const uint32_t bS  = tS + FF_A;
    __half* tHalf = (__half*)(smem_raw + FF_A);

    const uint32_t aLane =
        (uint32_t)(((warpm * 32) + (((lane >> 3) & 1) * 8) + (lane & 7)) * FPH
                   + (lane >> 4) * 8) * 2;
    const uint32_t bLane =
        (uint32_t)(((warpn * 32) + (((lane >> 4) & 1) * 8) + (lane & 7)) * HP
                   + ((lane >> 3) & 1) * 8) * 2;

    // load hn block (64 x 128 halves)
    #pragma unroll
    for (int i = 0; i < 4; i++) {
        int chunk = tid + i * 256;
        int m = chunk >> 4;              // 0..63
        int q = (chunk & 15) * 8;        // halves
        int gr = rowBase + m;
        cp_async16(hnS + (uint32_t)(m * FPH + q) * 2,
                   hn + (size_t)(gr < NNODES ? gr : 0) * DM + q,
                   (gr < NNODES) ? 16u : 0u);
    }
    asm volatile("cp.async.commit_group;" ::: "memory");

    float accO[2][4][4];
    #pragma unroll
    for (int ms = 0; ms < 2; ms++)
        #pragma unroll
        for (int ns = 0; ns < 4; ns++)
            #pragma unroll
            for (int q = 0; q < 4; q++) accO[ms][ns][q] = 0.0f;

    const float slp = __ldg(slope);

    // acc += A(smem halves, pitch FPH) @ B(global half K-major, rowstride bstr)
    auto run_gemm = [&](uint32_t aSm, const __half* Bbase, int bstr,
                        float (*acc)[4][4]) {
        auto loadB = [&](int buf, int kt) {
            int row = tid >> 1;              // 0..127 (n rows)
            int kq  = (tid & 1) * 8;
            cp_async16(bS + (uint32_t)(row * HP + kq) * 2 + buf * HSTAGEB,
                       Bbase + (size_t)row * bstr + kt * 16 + kq, 16u);
            asm volatile("cp.async.commit_group;" ::: "memory");
        };
        __syncthreads();   // all warps done with prior reads of stage buffers
        loadB(0, 0);
        loadB(1, 1);
        #pragma unroll
        for (int kt = 0; kt < 8; kt++) {
            if (kt + 1 < 8) asm volatile("cp.async.wait_group 1;" ::: "memory");
            else            asm volatile("cp.async.wait_group 0;" ::: "memory");
            __syncthreads();
            if (kt + 2 < 8) loadB((kt + 2) % NSTAGE, kt + 2);

            uint32_t a[2][4], b[4][2];
            const uint32_t ak = aSm + aLane + (uint32_t)(kt * 16) * 2;
            ldsm4(ak, a[0][0], a[0][1], a[0][2], a[0][3]);
            ldsm4(ak + 16 * FPH * 2, a[1][0], a[1][1], a[1][2], a[1][3]);
            const uint32_t bk = bS + bLane + (uint32_t)((kt % NSTAGE) * HSTAGEB);
            #pragma unroll
            for (int p = 0; p < 2; p++)
                ldsm4(bk + (uint32_t)(p * 16 * HP * 2),
                      b[2 * p][0], b[2 * p][1], b[2 * p + 1][0], b[2 * p + 1][1]);
            #pragma unroll
            for (int ms = 0; ms < 2; ms++)
                #pragma unroll
                for (int ns = 0; ns < 4; ns++)
                    mma_f16(acc[ms][ns], a[ms], b[ns]);
        }
    };

    #pragma unroll 1
    for (int c = 0; c < 4; c++) {
        // ---- stage 1: t_chunk = fp16(prelu(hn_s @ W1_chunk + b1_chunk)) ----
        float accT[2][4][4];
        #pragma unroll
        for (int ms = 0; ms < 2; ms++)
            #pragma unroll
            for (int ns = 0; ns < 4; ns++)
                #pragma unroll
                for (int q = 0; q < 4; q++) accT[ms][ns][q] = 0.0f;

        run_gemm(hnS, Bt1 + (size_t)(c * 128) * DM, DM, accT);

        __syncthreads();   // all warps done reading t_s (prev chunk stage 2)
        const float* b1c = b1 + c * 128;
        #pragma unroll
        for (int ms = 0; ms < 2; ms++) {
            #pragma unroll
            for (int half = 0; half < 2; half++) {
                int r = warpm * 32 + ms * 16 + half * 8 + (lane >> 2);
                #pragma unroll
                for (int ns = 0; ns < 4; ns++) {
                    int cl = warpn * 32 + ns * 8 + (lane & 3) * 2;
                    float v0 = accT[ms][ns][half * 2 + 0] + __ldg(b1c + cl);
                    float v1 = accT[ms][ns][half * 2 + 1] + __ldg(b1c + cl + 1);
                    v0 = (v0 >= 0.0f) ? v0 : slp * v0;
                    v1 = (v1 >= 0.0f) ? v1 : slp * v1;
                    *(__half2*)&tHalf[r * FPH + cl] = __floats2half2_rn(v0, v1);
                }
            }
        }
        __syncthreads();   // t_s visible

        // ---- stage 2: accO += t_s @ W2_chunk ----
        run_gemm(tS, Bt2 + (size_t)(c * 128), DFFH, accO);
    }

    // ---- final epilogue: out = accO + b2 + h; xr = fp16(out) ----
    #pragma unroll
    for (int ms = 0; ms < 2; ms++) {
        #pragma unroll
        for (int half = 0; half < 2; half++) {
            int r = rowBase + warpm * 32 + ms * 16 + half * 8 + (lane >> 2);
            if (r >= NNODES) continue;
            #pragma unroll
            for (int ns = 0; ns < 4; ns++) {
                int cl = warpn * 32 + ns * 8 + (lane & 3) * 2;
                float2 hv = *(const float2*)&hres[(size_t)r * DM + cl];
                float v0 = accO[ms][ns][half * 2 + 0] + __ldg(b2 + cl)     + hv.x;
                float v1 = accO[ms][ns][half * 2 + 1] + __ldg(b2 + cl + 1) + hv.y;
                *(float2*)&Cout[(size_t)r * DM + cl] = make_float2(v0, v1);
                *(__half2*)&xr[(size_t)r * DM + cl] = __floats2half2_rn(v0, v1);
            }
        }
    }
}

// ---------------- batched transpose + fp16 convert (z = layer) ---------------
__global__ void transpose_h(const float* __restrict__ in, __half* __restrict__ out,
                            int K, int N)
{
    __shared__ float tile[32][33];
    size_t mat = (size_t)blockIdx.z * K * N;
    int k0 = blockIdx.x * 32, n0 = blockIdx.y * 32;
    int tx = threadIdx.x, ty = threadIdx.y;
    #pragma unroll
    for (int i = 0; i < 4; i++)
        tile[ty + i * 8][tx] = in[mat + (size_t)(k0 + ty + i * 8) * N + n0 + tx];
    __syncthreads();
    #pragma unroll
    for (int i = 0; i < 4; i++)
        out[mat + (size_t)(n0 + ty + i * 8) * K + k0 + tx] =
            __float2half_rn(tile[tx][ty + i * 8]);
}

// ---------------- convert layer-0 input to fp16 ------------------------------
__global__ void conv_half(const float* __restrict__ in, __half* __restrict__ out, int n4)
{
    int i = blockIdx.x * blockDim.x + threadIdx.x;
    if (i >= n4) return;
    float4 v = ((const float4*)in)[i];
    __half2 h0 = __floats2half2_rn(v.x, v.y);
    __half2 h1 = __floats2half2_rn(v.z, v.w);
    ((__half2*)out)[i * 2]     = h0;
    ((__half2*)out)[i * 2 + 1] = h1;
}

// ---------------- CSR build (once per call) ----------------------------------
__global__ void csr_zero()
{
    int i = blockIdx.x * blockDim.x + threadIdx.x;
    if (i <= NNODES) g_cnt[i] = 0;
}
__global__ void csr_hist(const int* __restrict__ dst)
{
    int e = blockIdx.x * blockDim.x + threadIdx.x;
    if (e < NEDGES) atomicAdd(&g_cnt[dst[e] + 1], 1);
}
__global__ void __launch_bounds__(1024) csr_scan()
{
    __shared__ int warpsum[32];
    const int T = 1024, TOT = NNODES + 1;
    const int ITEMS = (TOT + T - 1) / T;
    int t = threadIdx.x, lane = t & 31, w = t >> 5;
    int base = t * ITEMS;
    int sum = 0;
    for (int i = 0; i < ITEMS; i++) {
        int idx = base + i;
        if (idx < TOT) sum += g_cnt[idx];
    }
    int v = sum;
    #pragma unroll
    for (int o = 1; o < 32; o <<= 1) {
        int u = __shfl_up_sync(0xFFFFFFFFu, v, o);
        if (lane >= o) v += u;
    }
    if (lane == 31) warpsum[w] = v;
    __syncthreads();
    if (w == 0) {
        int wv = warpsum[lane];
        #pragma unroll
        for (int o = 1; o < 32; o <<= 1) {
            int u = __shfl_up_sync(0xFFFFFFFFu, wv, o);
            if (lane >= o) wv += u;
        }
        warpsum[lane] = wv;
    }
    __syncthreads();
    int excl = v - sum + (w > 0 ? warpsum[w - 1] : 0);
    int run = excl;
    for (int i = 0; i < ITEMS; i++) {
        int idx = base + i;
        if (idx < TOT) {
            run += g_cnt[idx];
            g_cnt[idx] = run;
            if (idx < NNODES) g_wo[idx] = run;
        }
    }
}
__global__ void csr_scatter(const int* __restrict__ src, const int* __restrict__ dst)
{
    int e = blockIdx.x * blockDim.x + threadIdx.x;
    if (e >= NEDGES) return;
    int d = dst[e];
    int pos = atomicAdd(&g_wo[d], 1);
    g_adj[pos] = src[e];
}

// ---------------- warp-per-node: softmax-agg + PReLU + 2x LayerNorm ----------
__global__ void __launch_bounds__(256) gat_agg_ln(
    const float* __restrict__ conv_bias, const float* __restrict__ a_conv,
    const float* __restrict__ ln_scale,  const float* __restrict__ ln_bias)
{
    int n = blockIdx.x * 8 + (threadIdx.x >> 5);
    if (n >= NNODES) return;
    int lane = threadIdx.x & 31;
    int h = lane >> 2;

    float myer = (lane < HH) ? g_er[n * HH + lane] : 0.0f;
    int beg = g_cnt[n], end = g_cnt[n + 1];

    float acc[4] = {0.f, 0.f, 0.f, 0.f};
    float den = 0.f;
    int i = beg;
    #pragma unroll 1
    for (; i + 2 <= end; i += 2) {
        int s0 = g_adj[i], s1 = g_adj[i + 1];
        float ex0 = 0.f, ex1 = 0.f;
        if (lane < HH) {
            float l0 = g_el[s0 * HH + lane] + myer;
            float l1 = g_el[s1 * HH + lane] + myer;
            l0 = (l0 >= 0.0f) ? l0 : 0.2f * l0;
            l1 = (l1 >= 0.0f) ? l1 : 0.2f * l1;
            ex0 = __expf(l0);
            ex1 = __expf(l1);
            den += ex0 + ex1;
        }
        float eb0 = __shfl_sync(0xFFFFFFFFu, ex0, h);
        float eb1 = __shfl_sync(0xFFFFFFFFu, ex1, h);
        float4 z0 = *(const float4*)&g_z[(size_t)s0 * DM + lane * 4];
        float4 z1 = *(const float4*)&g_z[(size_t)s1 * DM + lane * 4];
        acc[0] = fmaf(eb0, z0.x, acc[0]);
        acc[1] = fmaf(eb0, z0.y, acc[1]);
        acc[2] = fmaf(eb0, z0.z, acc[2]);
        acc[3] = fmaf(eb0, z0.w, acc[3]);
        acc[0] = fmaf(eb1, z1.x, acc[0]);
        acc[1] = fmaf(eb1, z1.y, acc[1]);
        acc[2] = fmaf(eb1, z1.z, acc[2]);
        acc[3] = fmaf(eb1, z1.w, acc[3]);
    }
    if (i < end) {
        int s = g_adj[i];
        float ex = 0.f;
        if (lane < HH) {
            float lg = g_el[s * HH + lane] + myer;
            lg = (lg >= 0.0f) ? lg : 0.2f * lg;
            ex = __expf(lg);
            den += ex;
        }
        float exb = __shfl_sync(0xFFFFFFFFu, ex, h);
        float4 zv = *(const float4*)&g_z[(size_t)s * DM + lane * 4];
        acc[0] = fmaf(exb, zv.x, acc[0]);
        acc[1] = fmaf(exb, zv.y, acc[1]);
        acc[2] = fmaf(exb, zv.z, acc[2]);
        acc[3] = fmaf(exb, zv.w, acc[3]);
    }
    float denb = fmaxf(__shfl_sync(0xFFFFFFFFu, den, h), 1e-9f);

    int c = lane * 4;
    float4 cb = *(const float4*)&conv_bias[c];
    float a = __ldg(a_conv);
    float v[4] = {acc[0] / denb + cb.x, acc[1] / denb + cb.y,
                  acc[2] / denb + cb.z, acc[3] / denb + cb.w};
    #pragma unroll
    for (int q = 0; q < 4; q++) v[q] = (v[q] >= 0.0f) ? v[q] : a * v[q];

    float s = 0.f, s2 = 0.f;
    #pragma unroll
    for (int q = 0; q < 4; q++) { s += v[q]; s2 += v[q] * v[q]; }
    #pragma unroll
    for (int o = 16; o > 0; o >>= 1) {
        s  += __shfl_xor_sync(0xFFFFFFFFu, s, o);
        s2 += __shfl_xor_sync(0xFFFFFFFFu, s2, o);
    }
    float m = s * (1.0f / DM);
    float var = s2 * (1.0f / DM) - m * m;
    float inv = rsqrtf(var + 1e-5f);
    float4 lsc = *(const float4*)&ln_scale[c];
    float4 lbi = *(const float4*)&ln_bias[c];
    float hv[4];
    hv[0] = (v[0] - m) * inv * lsc.x + lbi.x;
    hv[1] = (v[1] - m) * inv * lsc.y + lbi.y;
    hv[2] = (v[2] - m) * inv * lsc.z + lbi.z;
    hv[3] = (v[3] - m) * inv * lsc.w + lbi.w;
    *(float4*)&g_h[(size_t)n * DM + c] = make_float4(hv[0], hv[1], hv[2], hv[3]);

    float t = 0.f, t2 = 0.f;
    #pragma unroll
    for (int q = 0; q < 4; q++) { t += hv[q]; t2 += hv[q] * hv[q]; }
    #pragma unroll
    for (int o = 16; o > 0; o >>= 1) {
        t  += __shfl_xor_sync(0xFFFFFFFFu, t, o);
        t2 += __shfl_xor_sync(0xFFFFFFFFu, t2, o);
    }
    float m2 = t * (1.0f / DM);
    float var2 = t2 * (1.0f / DM) - m2 * m2;
    float inv2 = rsqrtf(var2 + 1e-5f);
    float o0 = (hv[0] - m2) * inv2 * lsc.x + lbi.x;
    float o1 = (hv[1] - m2) * inv2 * lsc.y + lbi.y;
    float o2 = (hv[2] - m2) * inv2 * lsc.z + lbi.z;
    float o3 = (hv[3] - m2) * inv2 * lsc.w + lbi.w;
    *(__half2*)&g_hn[(size_t)n * DM + c]     = __floats2half2_rn(o0, o1);
    *(__half2*)&g_hn[(size_t)n * DM + c + 2] = __floats2half2_rn(o2, o3);
}

// ---------------- launcher ---------------------------------------------------
extern "C" void kernel_launch(void* const* d_in, const int* in_sizes, int n_in,
                              void* d_out, int out_size)
{
    const float* in_feats = (const float*)d_in[0];
    const int*   src      = (const int*)  d_in[1];
    const int*   dst      = (const int*)  d_in[2];
    const float* W        = (const float*)d_in[3];
    const float* attn_l   = (const float*)d_in[4];
    const float* attn_r   = (const float*)d_in[5];
    const float* conv_b   = (const float*)d_in[6];
    const float* a_conv   = (const float*)d_in[7];
    const float* ln_scale = (const float*)d_in[8];
    const float* ln_bias  = (const float*)d_in[9];
    const float* W1       = (const float*)d_in[10];
    const float* b1       = (const float*)d_in[11];
    const float* W2       = (const float*)d_in[12];
    const float* b2       = (const float*)d_in[13];
    const float* a_ff     = (const float*)d_in[14];
    float* out = (float*)d_out;

    float *zP, *hP;
    __half *xrP, *hnP, *btP;
    cudaGetSymbolAddress((void**)&zP,  g_z);
    cudaGetSymbolAddress((void**)&xrP, g_xr);
    cudaGetSymbolAddress((void**)&hP,  g_h);
    cudaGetSymbolAddress((void**)&hnP, g_hn);
    cudaGetSymbolAddress((void**)&btP, g_bt);

    cudaFuncSetAttribute(gemm_z, cudaFuncAttributeMaxDynamicSharedMemorySize, G0SMEM);
    cudaFuncSetAttribute(ff_fused, cudaFuncAttributeMaxDynamicSharedMemorySize, FF_SMEM);

    const int E_BLOCKS = (NEDGES + 255) / 256;
    const int RC_BLOCKS = (NNODES * DM / 4 + 255) / 256;

    // batched weight transposes -> fp16 (z = layer)
    transpose_h<<<dim3(DM / 32, DM / 32, 3), dim3(32, 8)>>>(W, btP + OFF_W(0), DM, DM);
    transpose_h<<<dim3(DM / 32, DFFH / 32, 3), dim3(32, 8)>>>(W1, btP + OFF_W1(0), DM, DFFH);
    transpose_h<<<dim3(DFFH / 32, DM / 32, 3), dim3(32, 8)>>>(W2, btP + OFF_W2(0), DFFH, DM);
    conv_half<<<RC_BLOCKS, 256>>>(in_feats, xrP, NNODES * DM / 4);

    // CSR build (graph fixed across layers)
    csr_zero<<<(NNODES + 256) / 256, 256>>>();
    csr_hist<<<E_BLOCKS, 256>>>(dst);
    csr_scan<<<1, 1024>>>();
    csr_scatter<<<E_BLOCKS, 256>>>(src, dst);

    for (int l = 0; l < LL; l++) {
        // z = xr @ W  (+ fused el/er)
        gemm_z<<<dim3(1, MTILES), 256, G0SMEM>>>(
            xrP, btP + OFF_W(l), zP,
            attn_l + (size_t)l * DM, attn_r + (size_t)l * DM);

        gat_agg_ln<<<(NNODES + 7) / 8, 256>>>(conv_b + (size_t)l * DM, a_conv + l,
                                              ln_scale + (size_t)l * DM,
                                              ln_bias + (size_t)l * DM);

        // out[l] = h + prelu(hn@W1+b1)@W2 + b2 ; xr = fp16(out[l])
        ff_fused<<<FTILES, 256, FF_SMEM>>>(
            hnP, btP + OFF_W1(l), btP + OFF_W2(l),
            b1 + (size_t)l * DFFH, a_ff + l, b2 + (size_t)l * DM,
            hP, out + (size_t)l * NNODES * DM, xrP);
    }
}